// round 11
// baseline (speedup 1.0000x reference)
#include <cuda_runtime.h>
#include <cuda_bf16.h>
#include <cuda_fp16.h>
#include <math.h>
#include <stdint.h>

#define BB   2
#define SS   2048
#define DD   2048
#define NHQ  16
#define NKVH 4
#define HDIM 128
#define MM   (BB*SS)       // 4096
#define KK   2048
#define NQ   (NHQ*HDIM)    // 2048
#define NKV  (NKVH*HDIM)   // 512

// ---------------- scratch (device globals; no allocation allowed) ----------
__device__ __half g_xhi[(size_t)MM*KK],  g_xlo[(size_t)MM*KK];
__device__ __half g_af[(size_t)MM*NQ];                 // attention out, fp16 single
__device__ __half g_qhi[(size_t)MM*NQ],  g_qlo[(size_t)MM*NQ];
__device__ __half g_kf[(size_t)MM*NKV];                // K fp16 single (roped)
__device__ __half g_vf[(size_t)MM*NKV];                // V fp16 single
__device__ __half g_wqT[(size_t)NQ*KK];
__device__ __half g_wkT[(size_t)NKV*KK];
__device__ __half g_wvT[(size_t)NKV*KK];
__device__ __half g_woT[(size_t)NQ*KK];
__device__ float2 g_rope[(size_t)SS*64];               // (cos, sin)

// ---------------- PTX helpers ----------------------------------------------
__device__ __forceinline__ uint32_t smem_u32(const void* p) {
    uint32_t a;
    asm("{ .reg .u64 t; cvta.to.shared.u64 t, %1; cvt.u32.u64 %0, t; }"
        : "=r"(a) : "l"(p));
    return a;
}

__device__ __forceinline__ void cp16(uint32_t s, const void* g) {
    asm volatile("cp.async.cg.shared.global [%0], [%1], 16;" :: "r"(s), "l"(g));
}
#define CP_COMMIT() asm volatile("cp.async.commit_group;" ::: "memory")
#define CP_WAIT(n)  asm volatile("cp.async.wait_group %0;" :: "n"(n) : "memory")

__device__ __forceinline__ void ldm_x4(uint32_t& r0, uint32_t& r1,
                                       uint32_t& r2, uint32_t& r3, uint32_t a) {
    asm volatile("ldmatrix.sync.aligned.m8n8.x4.shared.b16 {%0,%1,%2,%3}, [%4];"
                 : "=r"(r0), "=r"(r1), "=r"(r2), "=r"(r3) : "r"(a));
}
__device__ __forceinline__ void ldm_x4_t(uint32_t& r0, uint32_t& r1,
                                         uint32_t& r2, uint32_t& r3, uint32_t a) {
    asm volatile("ldmatrix.sync.aligned.m8n8.x4.trans.shared.b16 {%0,%1,%2,%3}, [%4];"
                 : "=r"(r0), "=r"(r1), "=r"(r2), "=r"(r3) : "r"(a));
}

__device__ __forceinline__ void mma16816h(float* c,
    uint32_t a0, uint32_t a1, uint32_t a2, uint32_t a3, uint32_t b0, uint32_t b1)
{
    asm volatile(
        "mma.sync.aligned.m16n8k16.row.col.f32.f16.f16.f32 "
        "{%0,%1,%2,%3}, {%4,%5,%6,%7}, {%8,%9}, {%0,%1,%2,%3};"
        : "+f"(c[0]), "+f"(c[1]), "+f"(c[2]), "+f"(c[3])
        : "r"(a0), "r"(a1), "r"(a2), "r"(a3), "r"(b0), "r"(b1));
}

__device__ __forceinline__ uint32_t pack_h2(float x, float y) {
    __half2 t = __floats2half2_rn(x, y);
    return *reinterpret_cast<uint32_t*>(&t);
}

__device__ __forceinline__ void store_hilo_h(__half* hi, __half* lo,
                                             size_t off, float a, float b)
{
    __half ha = __float2half(a), hb = __float2half(b);
    *(__half2*)(hi + off) = __halves2half2(ha, hb);
    *(__half2*)(lo + off) = __halves2half2(
        __float2half(a - __half2float(ha)),
        __float2half(b - __half2float(hb)));
}

// ---------------------------------------------------------------------------
// GEMM machinery. BK=32, pitch 80 B, 2-stage cp.async.
//   x2 variant: A hi/lo + B single (stage = 3 tiles)
//   x1 variant: A single + B single (stage = 2 tiles)
// ---------------------------------------------------------------------------
#define BK        32
#define ROWB      80
#define TILEB     (128 * ROWB)
#define OFF_AHI   0
#define OFF_ALO   (TILEB)
#define OFF_B     (2 * TILEB)
#define STAGEB    (3 * TILEB)          // 30720
#define GEMM_DSMEM (2 * STAGEB)        // 61440
#define OFF_B1    (TILEB)
#define STAGEB1   (2 * TILEB)          // 20480
#define GEMM1_DSMEM (2 * STAGEB1)      // 40960
#define NCHUNK    (KK / BK)            // 64

__device__ __forceinline__ void load_stage(uint32_t sBase,
    const __half* Ahi, const __half* Alo, const __half* Bs,
    int row0, int col0, int k0, int tid)
{
#pragma unroll
    for (int t = 0; t < 6; t++) {
        int i    = tid + t * 256;
        int tile = i >> 9;
        int w    = i & 511;
        int r    = w >> 2;
        int seg  = w & 3;
        const __half* src = (tile == 0) ? Ahi : (tile == 1) ? Alo : Bs;
        int rb = (tile < 2) ? row0 : col0;
        cp16(sBase + tile * TILEB + r * ROWB + seg * 16,
             src + (size_t)(rb + r) * KK + k0 + seg * 8);
    }
}

__device__ __forceinline__ void load_stage1(uint32_t sBase,
    const __half* As, const __half* Bs,
    int row0, int col0, int k0, int tid)
{
#pragma unroll
    for (int t = 0; t < 4; t++) {
        int i    = tid + t * 256;
        int tile = i >> 9;
        int w    = i & 511;
        int r    = w >> 2;
        int seg  = w & 3;
        const __half* src = (tile == 0) ? As : Bs;
        int rb = (tile == 0) ? row0 : col0;
        cp16(sBase + tile * TILEB + r * ROWB + seg * 16,
             src + (size_t)(rb + r) * KK + k0 + seg * 8);
    }
}

__device__ __forceinline__ void gemm_mainloop(uint32_t sBase,
    const __half* Ahi, const __half* Alo, const __half* Bs,
    int row0, int col0, int tid, int lane, int wr, int wc,
    float acc[4][4][4])
{
    load_stage(sBase, Ahi, Alo, Bs, row0, col0, 0, tid);
    CP_COMMIT();

#pragma unroll 1
    for (int c = 0; c < NCHUNK; c++) {
        const uint32_t st = sBase + (uint32_t)(c & 1) * STAGEB;
        if (c + 1 < NCHUNK) {
            load_stage(sBase + (uint32_t)((c + 1) & 1) * STAGEB,
                       Ahi, Alo, Bs, row0, col0, (c + 1) * BK, tid);
            CP_COMMIT();
            CP_WAIT(1);
        } else {
            CP_WAIT(0);
        }
        __syncthreads();

        const uint32_t aHiW = st + OFF_AHI + (uint32_t)(wr * 64) * ROWB;
        const uint32_t aLoW = st + OFF_ALO + (uint32_t)(wr * 64) * ROWB;
        const uint32_t bW   = st + OFF_B   + (uint32_t)(wc * 32) * ROWB;

#pragma unroll
        for (int ks = 0; ks < 2; ks++) {
            const uint32_t aoff = (uint32_t)((lane & 15) * ROWB
                                + (ks * 16 + ((lane >> 4) << 3)) * 2);
            uint32_t AH[4][4], AL[4][4];
#pragma unroll
            for (int am = 0; am < 4; am++) {
                ldm_x4(AH[am][0], AH[am][1], AH[am][2], AH[am][3],
                       aHiW + (uint32_t)(am * 16) * ROWB + aoff);
                ldm_x4(AL[am][0], AL[am][1], AL[am][2], AL[am][3],
                       aLoW + (uint32_t)(am * 16) * ROWB + aoff);
            }
            const uint32_t boff = (uint32_t)((((lane >> 4) << 3) + (lane & 7)) * ROWB
                                + (ks * 16 + ((lane >> 3) & 1) * 8) * 2);
            uint32_t Bx[2][4];
#pragma unroll
            for (int bn = 0; bn < 2; bn++)
                ldm_x4(Bx[bn][0], Bx[bn][1], Bx[bn][2], Bx[bn][3],
                       bW + (uint32_t)(bn * 16) * ROWB + boff);
#pragma unroll
            for (int am = 0; am < 4; am++)
#pragma unroll
                for (int an = 0; an < 4; an++) {
                    uint32_t b0 = Bx[an >> 1][(an & 1) * 2];
                    uint32_t b1 = Bx[an >> 1][(an & 1) * 2 + 1];
                    mma16816h(acc[am][an], AH[am][0], AH[am][1], AH[am][2], AH[am][3], b0, b1);
                    mma16816h(acc[am][an], AL[am][0], AL[am][1], AL[am][2], AL[am][3], b0, b1);
                }
        }
        __syncthreads();
    }
}

__device__ __forceinline__ void gemm_mainloop_x1(uint32_t sBase,
    const __half* As, const __half* Bs,
    int row0, int col0, int tid, int lane, int wr, int wc,
    float acc[4][4][4])
{
    load_stage1(sBase, As, Bs, row0, col0, 0, tid);
    CP_COMMIT();

#pragma unroll 1
    for (int c = 0; c < NCHUNK; c++) {
        const uint32_t st = sBase + (uint32_t)(c & 1) * STAGEB1;
        if (c + 1 < NCHUNK) {
            load_stage1(sBase + (uint32_t)((c + 1) & 1) * STAGEB1,
                        As, Bs, row0, col0, (c + 1) * BK, tid);
            CP_COMMIT();
            CP_WAIT(1);
        } else {
            CP_WAIT(0);
        }
        __syncthreads();

        const uint32_t aW = st + (uint32_t)(wr * 64) * ROWB;
        const uint32_t bW = st + OFF_B1 + (uint32_t)(wc * 32) * ROWB;

#pragma unroll
        for (int ks = 0; ks < 2; ks++) {
            const uint32_t aoff = (uint32_t)((lane & 15) * ROWB
                                + (ks * 16 + ((lane >> 4) << 3)) * 2);
            uint32_t A[4][4];
#pragma unroll
            for (int am = 0; am < 4; am++)
                ldm_x4(A[am][0], A[am][1], A[am][2], A[am][3],
                       aW + (uint32_t)(am * 16) * ROWB + aoff);
            const uint32_t boff = (uint32_t)((((lane >> 4) << 3) + (lane & 7)) * ROWB
                                + (ks * 16 + ((lane >> 3) & 1) * 8) * 2);
            uint32_t Bx[2][4];
#pragma unroll
            for (int bn = 0; bn < 2; bn++)
                ldm_x4(Bx[bn][0], Bx[bn][1], Bx[bn][2], Bx[bn][3],
                       bW + (uint32_t)(bn * 16) * ROWB + boff);
#pragma unroll
            for (int am = 0; am < 4; am++)
#pragma unroll
                for (int an = 0; an < 4; an++)
                    mma16816h(acc[am][an], A[am][0], A[am][1], A[am][2], A[am][3],
                              Bx[an >> 1][(an & 1) * 2], Bx[an >> 1][(an & 1) * 2 + 1]);
        }
        __syncthreads();
    }
}

// ---------------------------------------------------------------------------
// Fused QKV projection: 1-D grid of 768 CTAs.
// ---------------------------------------------------------------------------
__global__ __launch_bounds__(256) void gemm_qkv(
    const __half* __restrict__ xhi, const __half* __restrict__ xlo,
    const __half* __restrict__ wq, const __half* __restrict__ wk,
    const __half* __restrict__ wv,
    __half* __restrict__ qh, __half* __restrict__ ql,
    __half* __restrict__ kf, __half* __restrict__ vf,
    const float2* __restrict__ rope)
{
    extern __shared__ char dsm[];
    const uint32_t sBase = smem_u32(dsm);

    const int tid  = threadIdx.x;
    const int lane = tid & 31;
    const int wid  = tid >> 5;
    const int wr   = wid >> 2;
    const int wc   = wid & 3;

    const int bid = blockIdx.x;
    const __half* Bs;
    int row0, col0, N, mode;   // 0=Q rope hi/lo, 1=K rope single, 2=V single
    if (bid < 512) {
        row0 = (bid >> 4) * 128; col0 = (bid & 15) * 128;
        Bs = wq; N = NQ; mode = 0;
    } else if (bid < 640) {
        int i = bid - 512;
        row0 = (i >> 2) * 128; col0 = (i & 3) * 128;
        Bs = wk; N = NKV; mode = 1;
    } else {
        int i = bid - 640;
        row0 = (i >> 2) * 128; col0 = (i & 3) * 128;
        Bs = wv; N = NKV; mode = 2;
    }

    float acc[4][4][4];
#pragma unroll
    for (int i = 0; i < 4; i++)
#pragma unroll
        for (int j = 0; j < 4; j++)
#pragma unroll
            for (int l = 0; l < 4; l++) acc[i][j][l] = 0.0f;

    gemm_mainloop(sBase, xhi, xlo, Bs, row0, col0, tid, lane, wr, wc, acc);

    const int rbase = row0 + wr * 64;
    const int cbase = col0 + wc * 32;
#pragma unroll
    for (int am = 0; am < 4; am++)
#pragma unroll
        for (int an = 0; an < 4; an++) {
            float* cf = acc[am][an];
            int r  = rbase + am * 16 + (lane >> 2);
            int cc = cbase + an * 8 + (lane & 3) * 2;
            if (mode == 2) {
                *(__half2*)(vf + (size_t)r * N + cc)       = __floats2half2_rn(cf[0], cf[1]);
                *(__half2*)(vf + (size_t)(r + 8) * N + cc) = __floats2half2_rn(cf[2], cf[3]);
            } else {
                int p = (cc & 127) >> 1;
                float2 cs0 = rope[(size_t)(r & (SS - 1)) * 64 + p];
                float2 cs1 = rope[(size_t)((r + 8) & (SS - 1)) * 64 + p];
                float o0 = cf[0] * cs0.x - cf[1] * cs0.y;
                float o1 = cf[0] * cs0.y + cf[1] * cs0.x;
                float o2 = cf[2] * cs1.x - cf[3] * cs1.y;
                float o3 = cf[2] * cs1.y + cf[3] * cs1.x;
                if (mode == 0) {
                    store_hilo_h(qh, ql, (size_t)r * N + cc,       o0, o1);
                    store_hilo_h(qh, ql, (size_t)(r + 8) * N + cc, o2, o3);
                } else {
                    *(__half2*)(kf + (size_t)r * N + cc)       = __floats2half2_rn(o0, o1);
                    *(__half2*)(kf + (size_t)(r + 8) * N + cc) = __floats2half2_rn(o2, o3);
                }
            }
        }
}

// ---------------------------------------------------------------------------
// O-projection GEMM: A single fp16, fp32 C output
// ---------------------------------------------------------------------------
__global__ __launch_bounds__(256) void gemm_oproj(
    const __half* __restrict__ As, const __half* __restrict__ Bs,
    float* __restrict__ C, int N)
{
    extern __shared__ char dsm[];
    const uint32_t sBase = smem_u32(dsm);

    const int tid  = threadIdx.x;
    const int lane = tid & 31;
    const int wid  = tid >> 5;
    const int wr   = wid >> 2;
    const int wc   = wid & 3;
    const int row0 = blockIdx.y * 128;
    const int col0 = blockIdx.x * 128;

    float acc[4][4][4];
#pragma unroll
    for (int i = 0; i < 4; i++)
#pragma unroll
        for (int j = 0; j < 4; j++)
#pragma unroll
            for (int l = 0; l < 4; l++) acc[i][j][l] = 0.0f;

    gemm_mainloop_x1(sBase, As, Bs, row0, col0, tid, lane, wr, wc, acc);

    const int rbase = row0 + wr * 64;
    const int cbase = col0 + wc * 32;
#pragma unroll
    for (int am = 0; am < 4; am++)
#pragma unroll
        for (int an = 0; an < 4; an++) {
            float* cf = acc[am][an];
            int r  = rbase + am * 16 + (lane >> 2);
            int cc = cbase + an * 8 + (lane & 3) * 2;
            *(float2*)(C + (size_t)r * N + cc)       = make_float2(cf[0], cf[1]);
            *(float2*)(C + (size_t)(r + 8) * N + cc) = make_float2(cf[2], cf[3]);
        }
}

// ---------------------------------------------------------------------------
// Merged prep: rope table + x fp16 hi/lo split + 4 weight transposes (fp16)
// ---------------------------------------------------------------------------
#define PREP_GRID 27136

__device__ __forceinline__ void transpose_tile_h(
    const float* __restrict__ src, __half* __restrict__ dst,
    int N, int bx, int by, float (*t)[33], int tx, int ty)
{
    int k0 = by * 32, n0 = bx * 32;
#pragma unroll
    for (int j = 0; j < 32; j += 8)
        t[ty + j][tx] = src[(size_t)(k0 + ty + j) * N + n0 + tx];
    __syncthreads();
#pragma unroll
    for (int j = 0; j < 32; j += 8)
        dst[(size_t)(n0 + ty + j) * KK + k0 + tx] = __float2half(t[tx][ty + j]);
}

__global__ __launch_bounds__(256) void prep_kernel(
    const float* __restrict__ x,
    __half2* __restrict__ xhi2, __half2* __restrict__ xlo2,
    const float* __restrict__ Wq, const float* __restrict__ Wk,
    const float* __restrict__ Wv, const float* __restrict__ Wo,
    __half* __restrict__ wq, __half* __restrict__ wk,
    __half* __restrict__ wv, __half* __restrict__ wo,
    float2* __restrict__ ropet)
{
    __shared__ float t[32][33];
    const int bid = blockIdx.x;
    const int tid = threadIdx.x;

    if (bid < 512) {
        int i = bid * 256 + tid;
        int s = i >> 6, p = i & 63;
        float e   = (float)(2 * p) * (1.0f / 128.0f);
        float inv = 1.0f / powf(10000.0f, e);
        float sn, c;
        sincosf((float)s * inv, &sn, &c);
        ropet[i] = make_float2(c, sn);
    } else if (bid < 16896) {
        int i = (bid - 512) * 256 + tid;
        float2 v = ((const float2*)x)[i];
        __half hx = __float2half(v.x);
        __half hy = __float2half(v.y);
        xhi2[i] = __halves2half2(hx, hy);
        xlo2[i] = __halves2half2(__float2half(v.x - __half2float(hx)),
                                 __float2half(v.y - __half2float(hy)));
    } else {
        int r = bid - 16896;
        int tx = tid & 31, ty = tid >> 5;
        if (r < 4096)
            transpose_tile_h(Wq, wq, NQ,  r & 63, r >> 6, t, tx, ty);
        else if (r < 5120)
            transpose_tile_h(Wk, wk, NKV, (r - 4096) & 15, (r - 4096) >> 4, t, tx, ty);
        else if (r < 6144)
            transpose_tile_h(Wv, wv, NKV, (r - 5120) & 15, (r - 5120) >> 4, t, tx, ty);
        else
            transpose_tile_h(Wo, wo, NQ,  (r - 6144) & 63, (r - 6144) >> 6, t, tx, ty);
    }
}

// ---------------------------------------------------------------------------
// Flash attention: S = Qhi·K + Qlo·K (fp16 x2), P·V fp16. Causal, GQA 4:1.
// LPT 1-D grid. 3-stage KV ring; epilogue writes single fp16.
// ---------------------------------------------------------------------------
#define AP      272
#define QTB     (128 * AP)
#define KVTB    (64 * AP)
#define KVB     (2 * QTB)
#define KVSTG   (2 * KVTB)
#define ATTN_SMEM (2 * QTB + 3 * KVSTG)   // 174080

__device__ __forceinline__ void load_kv_tile(uint32_t sb, uint32_t stg,
    const __half* kf, const __half* vf, int k0, int tid)
{
#pragma unroll
    for (int t = 0; t < 8; t++) {
        int i  = tid + t * 256;
        int m  = i >> 10;
        int w  = i & 1023;
        int r  = w >> 4;
        int sg = w & 15;
        const __half* src = m ? vf : kf;
        cp16(sb + stg + (uint32_t)m * KVTB + (uint32_t)(r * AP + sg * 16),
             src + (size_t)(k0 + r) * NKV + sg * 8);
    }
}

__global__ __launch_bounds__(256) void attn_mma(
    const __half* __restrict__ qhi, const __half* __restrict__ qlo,
    const __half* __restrict__ kf, const __half* __restrict__ vf,
    __half* __restrict__ oa)
{
    extern __shared__ char sm[];
    const uint32_t sb = smem_u32(sm);

    const int bid = blockIdx.x;
    const int qt  = (SS / 128 - 1) - (bid >> 5);
    const int hb  = bid & 31;
    const int h   = hb & 15;
    const int b   = hb >> 4;
    const int kvh = h >> 2;
    const int q0  = qt * 128;

    const int tid  = threadIdx.x;
    const int lane = tid & 31;
    const int wid  = tid >> 5;
    const int wq0  = wid * 16;
    const int gr   = lane >> 2;

    const __half* qhb = qhi + ((size_t)b * SS + q0) * NQ + h * HDIM;
    const __half* qlb = qlo + ((size_t)b * SS + q0) * NQ + h * HDIM;
    const __half* kfb = kf + (size_t)b * SS * NKV + kvh * HDIM;
    const __half* vfb = vf + (size_t)b * SS * NKV + kvh * HDIM;

    const int ntiles = 2 * qt + 2;

#pragma unroll
    for (int t = 0; t < 16; t++) {
        int i   = tid + t * 256;
        int hl  = i >> 11;
        int w   = i & 2047;
        int r   = w >> 4;
        int sg  = w & 15;
        const __half* src = hl ? qlb : qhb;
        cp16(sb + (uint32_t)hl * QTB + (uint32_t)(r * AP + sg * 16),
             src + (size_t)r * NQ + sg * 8);
    }
    load_kv_tile(sb, KVB, kfb, vfb, 0, tid);
    CP_COMMIT();
    load_kv_tile(sb, KVB + KVSTG, kfb, vfb, 64, tid);
    CP_COMMIT();

    float oacc[16][4];
#pragma unroll
    for (int j = 0; j < 16; j++)
#pragma unroll
        for (int e = 0; e < 4; e++) oacc[j][e] = 0.0f;
    float mA = -1e30f, mB = -1e30f, lA = 0.0f, lB = 0.0f;

    const float scale = 0.08838834764831845f;
    const int rAg = q0 + wq0 + gr;
    const int rBg = rAg + 8;

#pragma unroll 1
    for (int t = 0; t < ntiles; t++) {
        if (t + 2 < ntiles) {
            load_kv_tile(sb, KVB + (uint32_t)((t + 2) % 3) * KVSTG,
                         kfb, vfb, (t + 2) * 64, tid);
            CP_COMMIT();
            CP_WAIT(2);
        } else if (t + 1 < ntiles) {
            CP_WAIT(1);
        } else {
            CP_WAIT(0);
        }
        __syncthreads();

        const uint32_t kv = sb + KVB + (uint32_t)(t % 3) * KVSTG;

        // ---- S = Q @ K^T (fp16 x2) ----
        float sacc[8][4];
#pragma unroll
        for (int j = 0; j < 8; j++)
#pragma unroll
            for (int e = 0; e < 4; e++) sacc[j][e] = 0.0f;

        const uint32_t aB = sb + (uint32_t)wq0 * AP;
#pragma unroll
        for (int c = 0; c < 8; c++) {
            const uint32_t ao = (uint32_t)((lane & 15) * AP
                              + (c * 16 + ((lane >> 4) << 3)) * 2);
            uint32_t ah0, ah1, ah2, ah3, al0, al1, al2, al3;
            ldm_x4(ah0, ah1, ah2, ah3, aB + ao);
            ldm_x4(al0, al1, al2, al3, aB + QTB + ao);
#pragma unroll
            for (int g = 0; g < 4; g++) {
                const uint32_t bo = (uint32_t)((g * 16 + ((lane >> 4) << 3) + (lane & 7)) * AP
                                  + (c * 16 + ((lane >> 3) & 1) * 8) * 2);
                uint32_t bh0, bh1, bh2, bh3;
                ldm_x4(bh0, bh1, bh2, bh3, kv + bo);
                mma16816h(sacc[2 * g],     ah0, ah1, ah2, ah3, bh0, bh1);
                mma16816h(sacc[2 * g + 1], ah0, ah1, ah2, ah3, bh2, bh3);
                mma16816h(sacc[2 * g],     al0, al1, al2, al3, bh0, bh1);
                mma16816h(sacc[2 * g + 1], al0, al1, al2, al3, bh2, bh3);
            }
        }

#pragma unroll
        for (int j = 0; j < 8; j++)
#pragma unroll
            for (int e = 0; e < 4; e++) sacc[j][e] *= scale;

        if (t >= 2 * qt) {
#pragma unroll
            for (int j = 0; j < 8; j++) {
                int col = t * 64 + j * 8 + 2 * (lane & 3);
                if (col     > rAg) sacc[j][0] = -1e30f;
                if (col + 1 > rAg) sacc[j][1] = -1e30f;
                if (col     > rBg) sacc[j][2] = -1e30f;
                if (col + 1 > rBg) sacc[j][3] = -1e30f;
            }
        }

        // ---- online softmax ----
        float mxA = -1e30f, mxB = -1e30f;
#pragma unroll
        for (int j = 0; j < 8; j++) {
            mxA = fmaxf(mxA, fmaxf(sacc[j][0], sacc[j][1]));
            mxB = fmaxf(mxB, fmaxf(sacc[j][2], sacc[j][3]));
        }
        mxA = fmaxf(mxA, __shfl_xor_sync(0xffffffffu, mxA, 1));
        mxA = fmaxf(mxA, __shfl_xor_sync(0xffffffffu, mxA, 2));
        mxB = fmaxf(mxB, __shfl_xor_sync(0xffffffffu, mxB, 1));
        mxB = fmaxf(mxB, __shfl_xor_sync(0xffffffffu, mxB, 2));

        float mnA = fmaxf(mA, mxA), mnB = fmaxf(mB, mxB);
        float facA = __expf(mA - mnA), facB = __expf(mB - mnB);
        float sA = 0.0f, sB = 0.0f;
#pragma unroll
        for (int j = 0; j < 8; j++) {
            float p0 = __expf(sacc[j][0] - mnA);
            float p1 = __expf(sacc[j][1] - mnA);
            float p2 = __expf(sacc[j][2] - mnB);
            float p3 = __expf(sacc[j][3] - mnB);
            sacc[j][0] = p0; sacc[j][1] = p1; sacc[j][2] = p2; sacc[j][3] = p3;
            sA += p0 + p1; sB += p2 + p3;
        }
        sA += __shfl_xor_sync(0xffffffffu, sA, 1);
        sA += __shfl_xor_sync(0xffffffffu, sA, 2);
        sB += __shfl_xor_sync(0xffffffffu, sB, 1);
        sB += __shfl_xor_sync(0xffffffffu, sB, 2);
        lA = lA * facA + sA; lB = lB * facB + sB;
        mA = mnA; mB = mnB;
#pragma unroll
        for (int j = 0; j < 16; j++) {
            oacc[j][0] *= facA; oacc[j][1] *= facA;
            oacc[j][2] *= facB; oacc[j][3] *= facB;
        }

        // ---- O += P @ V (single fp16 pass) ----
#pragma unroll
        for (int kc = 0; kc < 4; kc++) {
            const int j0 = 2 * kc, j1 = 2 * kc + 1;
            uint32_t ph[4];
            ph[0] = pack_h2(sacc[j0][0], sacc[j0][1]);
            ph[1] = pack_h2(sacc[j0][2], sacc[j0][3]);
            ph[2] = pack_h2(sacc[j1][0], sacc[j1][1]);
            ph[3] = pack_h2(sacc[j1][2], sacc[j1][3]);
#pragma unroll
            for (int bn = 0; bn < 8; bn++) {
                const uint32_t rowsel =
                    (uint32_t)((kc * 16 + ((lane >> 4) << 3) + (lane & 7)) * AP
                             + (bn * 16 + ((lane >> 3) & 1) * 8) * 2);
                uint32_t r0, r1, r2, r3;
                ldm_x4_t(r0, r1, r2, r3, kv + KVTB + rowsel);
                mma16816h(oacc[2 * bn],     ph[0], ph[1], ph[2], ph[3], r0, r2);
                mma16816h(oacc[2 * bn + 1], ph[0], ph[1], ph[2], ph[3], r1, r3);
            }
        }
        __syncthreads();
    }

    const float invA = 1.0f / lA, invB = 1.0f / lB;
    const size_t rowA = ((size_t)b * SS + rAg) * NQ;
    const size_t rowB = ((size_t)b * SS + rBg) * NQ;
#pragma unroll
    for (int j = 0; j < 16; j++) {
        int col = h * HDIM + j * 8 + 2 * (lane & 3);
        *(__half2*)(oa + rowA + col) = __floats2half2_rn(oacc[j][0] * invA, oacc[j][1] * invA);
        *(__half2*)(oa + rowB + col) = __floats2half2_rn(oacc[j][2] * invB, oacc[j][3] * invB);
    }
}

// ---------------------------------------------------------------------------
extern "C" void kernel_launch(void* const* d_in, const int* in_sizes, int n_in,
                              void* d_out, int out_size)
{
    const float* x  = (const float*)d_in[0];
    const float* Wq = (const float*)d_in[2];
    const float* Wk = (const float*)d_in[3];
    const float* Wv = (const float*)d_in[4];
    const float* Wo = (const float*)d_in[5];
    float* out = (float*)d_out;

    __half *xhi, *xlo, *af, *qh, *ql, *kf, *vf;
    __half *wq, *wk, *wv, *wo;
    float2* rope;
    (void)cudaGetSymbolAddress((void**)&xhi, g_xhi);
    (void)cudaGetSymbolAddress((void**)&xlo, g_xlo);
    (void)cudaGetSymbolAddress((void**)&af, g_af);
    (void)cudaGetSymbolAddress((void**)&qh, g_qhi);
    (void)cudaGetSymbolAddress((void**)&ql, g_qlo);
    (void)cudaGetSymbolAddress((void**)&kf, g_kf);
    (void)cudaGetSymbolAddress((void**)&vf, g_vf);
    (void)cudaGetSymbolAddress((void**)&wq, g_wqT);
    (void)cudaGetSymbolAddress((void**)&wk, g_wkT);
    (void)cudaGetSymbolAddress((void**)&wv, g_wvT);
    (void)cudaGetSymbolAddress((void**)&wo, g_woT);
    (void)cudaGetSymbolAddress((void**)&rope, g_rope);

    (void)cudaFuncSetAttribute(gemm_qkv,
                               cudaFuncAttributeMaxDynamicSharedMemorySize, GEMM_DSMEM);
    (void)cudaFuncSetAttribute(gemm_oproj,
                               cudaFuncAttributeMaxDynamicSharedMemorySize, GEMM1_DSMEM);
    (void)cudaFuncSetAttribute(attn_mma,
                               cudaFuncAttributeMaxDynamicSharedMemorySize, ATTN_SMEM);

    // 1) merged prep
    prep_kernel<<<PREP_GRID, 256>>>(x,
                                    (__half2*)xhi, (__half2*)xlo,
                                    Wq, Wk, Wv, Wo,
                                    wq, wk, wv, wo, rope);

    // 2) fused QKV projection (fp16 x2)
    gemm_qkv<<<768, 256, GEMM_DSMEM>>>(xhi, xlo, wq, wk, wv,
                                       qh, ql, kf, vf, rope);

    // 3) attention (fp16 x2 S, fp16 PV); writes single-fp16 attention output
    attn_mma<<<(SS / 128) * NHQ * BB, 256, ATTN_SMEM>>>(qh, ql, kf, vf, af);

    // 4) output projection (fp16 x1) -> fp32 out
    gemm_oproj<<<dim3(NQ / 128, MM / 128), 256, GEMM1_DSMEM>>>(af, wo, out, NQ);
}

// round 12
// speedup vs baseline: 1.5367x; 1.5367x over previous
#include <cuda_runtime.h>
#include <cuda_bf16.h>
#include <cuda_fp16.h>
#include <math.h>
#include <stdint.h>

#define BB   2
#define SS   2048
#define DD   2048
#define NHQ  16
#define NKVH 4
#define HDIM 128
#define MM   (BB*SS)       // 4096
#define KK   2048
#define NQ   (NHQ*HDIM)    // 2048
#define NKV  (NKVH*HDIM)   // 512

// ---------------- scratch (device globals; no allocation allowed) ----------
__device__ __half g_xhi[(size_t)MM*KK],  g_xlo[(size_t)MM*KK];
__device__ __half g_af[(size_t)MM*NQ];                 // attention out, fp16 single
__device__ __half g_qhi[(size_t)MM*NQ],  g_qlo[(size_t)MM*NQ];
__device__ __half g_kf[(size_t)MM*NKV];                // K fp16 single (roped)
__device__ __half g_vf[(size_t)MM*NKV];                // V fp16 single
__device__ __half g_wqT[(size_t)NQ*KK];
__device__ __half g_wkT[(size_t)NKV*KK];
__device__ __half g_wvT[(size_t)NKV*KK];
__device__ __half g_woT[(size_t)NQ*KK];
__device__ float2 g_rope[(size_t)SS*64];               // (cos, sin)

// ---------------- PTX helpers ----------------------------------------------
__device__ __forceinline__ uint32_t smem_u32(const void* p) {
    uint32_t a;
    asm("{ .reg .u64 t; cvta.to.shared.u64 t, %1; cvt.u32.u64 %0, t; }"
        : "=r"(a) : "l"(p));
    return a;
}

__device__ __forceinline__ void cp16(uint32_t s, const void* g) {
    asm volatile("cp.async.cg.shared.global [%0], [%1], 16;" :: "r"(s), "l"(g));
}
#define CP_COMMIT() asm volatile("cp.async.commit_group;" ::: "memory")
#define CP_WAIT(n)  asm volatile("cp.async.wait_group %0;" :: "n"(n) : "memory")

__device__ __forceinline__ void ldm_x4(uint32_t& r0, uint32_t& r1,
                                       uint32_t& r2, uint32_t& r3, uint32_t a) {
    asm volatile("ldmatrix.sync.aligned.m8n8.x4.shared.b16 {%0,%1,%2,%3}, [%4];"
                 : "=r"(r0), "=r"(r1), "=r"(r2), "=r"(r3) : "r"(a));
}
__device__ __forceinline__ void ldm_x4_t(uint32_t& r0, uint32_t& r1,
                                         uint32_t& r2, uint32_t& r3, uint32_t a) {
    asm volatile("ldmatrix.sync.aligned.m8n8.x4.trans.shared.b16 {%0,%1,%2,%3}, [%4];"
                 : "=r"(r0), "=r"(r1), "=r"(r2), "=r"(r3) : "r"(a));
}

__device__ __forceinline__ void mma16816h(float* c,
    uint32_t a0, uint32_t a1, uint32_t a2, uint32_t a3, uint32_t b0, uint32_t b1)
{
    asm volatile(
        "mma.sync.aligned.m16n8k16.row.col.f32.f16.f16.f32 "
        "{%0,%1,%2,%3}, {%4,%5,%6,%7}, {%8,%9}, {%0,%1,%2,%3};"
        : "+f"(c[0]), "+f"(c[1]), "+f"(c[2]), "+f"(c[3])
        : "r"(a0), "r"(a1), "r"(a2), "r"(a3), "r"(b0), "r"(b1));
}

__device__ __forceinline__ uint32_t pack_h2(float x, float y) {
    __half2 t = __floats2half2_rn(x, y);
    return *reinterpret_cast<uint32_t*>(&t);
}

__device__ __forceinline__ void store_hilo_h(__half* hi, __half* lo,
                                             size_t off, float a, float b)
{
    __half ha = __float2half(a), hb = __float2half(b);
    *(__half2*)(hi + off) = __halves2half2(ha, hb);
    *(__half2*)(lo + off) = __halves2half2(
        __float2half(a - __half2float(ha)),
        __float2half(b - __half2float(hb)));
}

// ---------------------------------------------------------------------------
// GEMM machinery. BK=32, pitch 80 B, 2-stage cp.async.
//   x2 variant: A hi/lo + B single (stage = 3 tiles)
//   x1 variant: A single + B single (stage = 2 tiles)
// ---------------------------------------------------------------------------
#define BK        32
#define ROWB      80
#define TILEB     (128 * ROWB)
#define OFF_AHI   0
#define OFF_ALO   (TILEB)
#define OFF_B     (2 * TILEB)
#define STAGEB    (3 * TILEB)          // 30720
#define GEMM_DSMEM (2 * STAGEB)        // 61440
#define OFF_B1    (TILEB)
#define STAGEB1   (2 * TILEB)          // 20480
#define GEMM1_DSMEM (2 * STAGEB1)      // 40960
#define NCHUNK    (KK / BK)            // 64

__device__ __forceinline__ void load_stage(uint32_t sBase,
    const __half* Ahi, const __half* Alo, const __half* Bs,
    int row0, int col0, int k0, int tid)
{
#pragma unroll
    for (int t = 0; t < 6; t++) {
        int i    = tid + t * 256;
        int tile = i >> 9;
        int w    = i & 511;
        int r    = w >> 2;
        int seg  = w & 3;
        const __half* src = (tile == 0) ? Ahi : (tile == 1) ? Alo : Bs;
        int rb = (tile < 2) ? row0 : col0;
        cp16(sBase + tile * TILEB + r * ROWB + seg * 16,
             src + (size_t)(rb + r) * KK + k0 + seg * 8);
    }
}

__device__ __forceinline__ void load_stage1(uint32_t sBase,
    const __half* As, const __half* Bs,
    int row0, int col0, int k0, int tid)
{
#pragma unroll
    for (int t = 0; t < 4; t++) {
        int i    = tid + t * 256;
        int tile = i >> 9;
        int w    = i & 511;
        int r    = w >> 2;
        int seg  = w & 3;
        const __half* src = (tile == 0) ? As : Bs;
        int rb = (tile == 0) ? row0 : col0;
        cp16(sBase + tile * TILEB + r * ROWB + seg * 16,
             src + (size_t)(rb + r) * KK + k0 + seg * 8);
    }
}

__device__ __forceinline__ void gemm_mainloop(uint32_t sBase,
    const __half* Ahi, const __half* Alo, const __half* Bs,
    int row0, int col0, int tid, int lane, int wr, int wc,
    float acc[4][4][4])
{
    load_stage(sBase, Ahi, Alo, Bs, row0, col0, 0, tid);
    CP_COMMIT();

#pragma unroll 1
    for (int c = 0; c < NCHUNK; c++) {
        const uint32_t st = sBase + (uint32_t)(c & 1) * STAGEB;
        if (c + 1 < NCHUNK) {
            load_stage(sBase + (uint32_t)((c + 1) & 1) * STAGEB,
                       Ahi, Alo, Bs, row0, col0, (c + 1) * BK, tid);
            CP_COMMIT();
            CP_WAIT(1);
        } else {
            CP_WAIT(0);
        }
        __syncthreads();

        const uint32_t aHiW = st + OFF_AHI + (uint32_t)(wr * 64) * ROWB;
        const uint32_t aLoW = st + OFF_ALO + (uint32_t)(wr * 64) * ROWB;
        const uint32_t bW   = st + OFF_B   + (uint32_t)(wc * 32) * ROWB;

#pragma unroll
        for (int ks = 0; ks < 2; ks++) {
            const uint32_t aoff = (uint32_t)((lane & 15) * ROWB
                                + (ks * 16 + ((lane >> 4) << 3)) * 2);
            uint32_t AH[4][4], AL[4][4];
#pragma unroll
            for (int am = 0; am < 4; am++) {
                ldm_x4(AH[am][0], AH[am][1], AH[am][2], AH[am][3],
                       aHiW + (uint32_t)(am * 16) * ROWB + aoff);
                ldm_x4(AL[am][0], AL[am][1], AL[am][2], AL[am][3],
                       aLoW + (uint32_t)(am * 16) * ROWB + aoff);
            }
            const uint32_t boff = (uint32_t)((((lane >> 4) << 3) + (lane & 7)) * ROWB
                                + (ks * 16 + ((lane >> 3) & 1) * 8) * 2);
            uint32_t Bx[2][4];
#pragma unroll
            for (int bn = 0; bn < 2; bn++)
                ldm_x4(Bx[bn][0], Bx[bn][1], Bx[bn][2], Bx[bn][3],
                       bW + (uint32_t)(bn * 16) * ROWB + boff);
#pragma unroll
            for (int am = 0; am < 4; am++)
#pragma unroll
                for (int an = 0; an < 4; an++) {
                    uint32_t b0 = Bx[an >> 1][(an & 1) * 2];
                    uint32_t b1 = Bx[an >> 1][(an & 1) * 2 + 1];
                    mma16816h(acc[am][an], AH[am][0], AH[am][1], AH[am][2], AH[am][3], b0, b1);
                    mma16816h(acc[am][an], AL[am][0], AL[am][1], AL[am][2], AL[am][3], b0, b1);
                }
        }
        __syncthreads();
    }
}

__device__ __forceinline__ void gemm_mainloop_x1(uint32_t sBase,
    const __half* As, const __half* Bs,
    int row0, int col0, int tid, int lane, int wr, int wc,
    float acc[4][4][4])
{
    load_stage1(sBase, As, Bs, row0, col0, 0, tid);
    CP_COMMIT();

#pragma unroll 1
    for (int c = 0; c < NCHUNK; c++) {
        const uint32_t st = sBase + (uint32_t)(c & 1) * STAGEB1;
        if (c + 1 < NCHUNK) {
            load_stage1(sBase + (uint32_t)((c + 1) & 1) * STAGEB1,
                        As, Bs, row0, col0, (c + 1) * BK, tid);
            CP_COMMIT();
            CP_WAIT(1);
        } else {
            CP_WAIT(0);
        }
        __syncthreads();

        const uint32_t aW = st + (uint32_t)(wr * 64) * ROWB;
        const uint32_t bW = st + OFF_B1 + (uint32_t)(wc * 32) * ROWB;

#pragma unroll
        for (int ks = 0; ks < 2; ks++) {
            const uint32_t aoff = (uint32_t)((lane & 15) * ROWB
                                + (ks * 16 + ((lane >> 4) << 3)) * 2);
            uint32_t A[4][4];
#pragma unroll
            for (int am = 0; am < 4; am++)
                ldm_x4(A[am][0], A[am][1], A[am][2], A[am][3],
                       aW + (uint32_t)(am * 16) * ROWB + aoff);
            const uint32_t boff = (uint32_t)((((lane >> 4) << 3) + (lane & 7)) * ROWB
                                + (ks * 16 + ((lane >> 3) & 1) * 8) * 2);
            uint32_t Bx[2][4];
#pragma unroll
            for (int bn = 0; bn < 2; bn++)
                ldm_x4(Bx[bn][0], Bx[bn][1], Bx[bn][2], Bx[bn][3],
                       bW + (uint32_t)(bn * 16) * ROWB + boff);
#pragma unroll
            for (int am = 0; am < 4; am++)
#pragma unroll
                for (int an = 0; an < 4; an++)
                    mma16816h(acc[am][an], A[am][0], A[am][1], A[am][2], A[am][3],
                              Bx[an >> 1][(an & 1) * 2], Bx[an >> 1][(an & 1) * 2 + 1]);
        }
        __syncthreads();
    }
}

// ---------------------------------------------------------------------------
// Fused QKV projection: 1-D grid of 768 CTAs.
// ---------------------------------------------------------------------------
__global__ __launch_bounds__(256) void gemm_qkv(
    const __half* __restrict__ xhi, const __half* __restrict__ xlo,
    const __half* __restrict__ wq, const __half* __restrict__ wk,
    const __half* __restrict__ wv,
    __half* __restrict__ qh, __half* __restrict__ ql,
    __half* __restrict__ kf, __half* __restrict__ vf,
    const float2* __restrict__ rope)
{
    extern __shared__ char dsm[];
    const uint32_t sBase = smem_u32(dsm);

    const int tid  = threadIdx.x;
    const int lane = tid & 31;
    const int wid  = tid >> 5;
    const int wr   = wid >> 2;
    const int wc   = wid & 3;

    const int bid = blockIdx.x;
    const __half* Bs;
    int row0, col0, N, mode;   // 0=Q rope hi/lo, 1=K rope single, 2=V single
    if (bid < 512) {
        row0 = (bid >> 4) * 128; col0 = (bid & 15) * 128;
        Bs = wq; N = NQ; mode = 0;
    } else if (bid < 640) {
        int i = bid - 512;
        row0 = (i >> 2) * 128; col0 = (i & 3) * 128;
        Bs = wk; N = NKV; mode = 1;
    } else {
        int i = bid - 640;
        row0 = (i >> 2) * 128; col0 = (i & 3) * 128;
        Bs = wv; N = NKV; mode = 2;
    }

    float acc[4][4][4];
#pragma unroll
    for (int i = 0; i < 4; i++)
#pragma unroll
        for (int j = 0; j < 4; j++)
#pragma unroll
            for (int l = 0; l < 4; l++) acc[i][j][l] = 0.0f;

    gemm_mainloop(sBase, xhi, xlo, Bs, row0, col0, tid, lane, wr, wc, acc);

    const int rbase = row0 + wr * 64;
    const int cbase = col0 + wc * 32;
#pragma unroll
    for (int am = 0; am < 4; am++)
#pragma unroll
        for (int an = 0; an < 4; an++) {
            float* cf = acc[am][an];
            int r  = rbase + am * 16 + (lane >> 2);
            int cc = cbase + an * 8 + (lane & 3) * 2;
            if (mode == 2) {
                *(__half2*)(vf + (size_t)r * N + cc)       = __floats2half2_rn(cf[0], cf[1]);
                *(__half2*)(vf + (size_t)(r + 8) * N + cc) = __floats2half2_rn(cf[2], cf[3]);
            } else {
                int p = (cc & 127) >> 1;
                float2 cs0 = rope[(size_t)(r & (SS - 1)) * 64 + p];
                float2 cs1 = rope[(size_t)((r + 8) & (SS - 1)) * 64 + p];
                float o0 = cf[0] * cs0.x - cf[1] * cs0.y;
                float o1 = cf[0] * cs0.y + cf[1] * cs0.x;
                float o2 = cf[2] * cs1.x - cf[3] * cs1.y;
                float o3 = cf[2] * cs1.y + cf[3] * cs1.x;
                if (mode == 0) {
                    store_hilo_h(qh, ql, (size_t)r * N + cc,       o0, o1);
                    store_hilo_h(qh, ql, (size_t)(r + 8) * N + cc, o2, o3);
                } else {
                    *(__half2*)(kf + (size_t)r * N + cc)       = __floats2half2_rn(o0, o1);
                    *(__half2*)(kf + (size_t)(r + 8) * N + cc) = __floats2half2_rn(o2, o3);
                }
            }
        }
}

// ---------------------------------------------------------------------------
// O-projection GEMM: A single fp16, fp32 C output
// ---------------------------------------------------------------------------
__global__ __launch_bounds__(256) void gemm_oproj(
    const __half* __restrict__ As, const __half* __restrict__ Bs,
    float* __restrict__ C, int N)
{
    extern __shared__ char dsm[];
    const uint32_t sBase = smem_u32(dsm);

    const int tid  = threadIdx.x;
    const int lane = tid & 31;
    const int wid  = tid >> 5;
    const int wr   = wid >> 2;
    const int wc   = wid & 3;
    const int row0 = blockIdx.y * 128;
    const int col0 = blockIdx.x * 128;

    float acc[4][4][4];
#pragma unroll
    for (int i = 0; i < 4; i++)
#pragma unroll
        for (int j = 0; j < 4; j++)
#pragma unroll
            for (int l = 0; l < 4; l++) acc[i][j][l] = 0.0f;

    gemm_mainloop_x1(sBase, As, Bs, row0, col0, tid, lane, wr, wc, acc);

    const int rbase = row0 + wr * 64;
    const int cbase = col0 + wc * 32;
#pragma unroll
    for (int am = 0; am < 4; am++)
#pragma unroll
        for (int an = 0; an < 4; an++) {
            float* cf = acc[am][an];
            int r  = rbase + am * 16 + (lane >> 2);
            int cc = cbase + an * 8 + (lane & 3) * 2;
            *(float2*)(C + (size_t)r * N + cc)       = make_float2(cf[0], cf[1]);
            *(float2*)(C + (size_t)(r + 8) * N + cc) = make_float2(cf[2], cf[3]);
        }
}

// ---------------------------------------------------------------------------
// Merged prep: rope table + x fp16 hi/lo split + 4 weight transposes (fp16)
// ---------------------------------------------------------------------------
#define PREP_GRID 27136

__device__ __forceinline__ void transpose_tile_h(
    const float* __restrict__ src, __half* __restrict__ dst,
    int N, int bx, int by, float (*t)[33], int tx, int ty)
{
    int k0 = by * 32, n0 = bx * 32;
#pragma unroll
    for (int j = 0; j < 32; j += 8)
        t[ty + j][tx] = src[(size_t)(k0 + ty + j) * N + n0 + tx];
    __syncthreads();
#pragma unroll
    for (int j = 0; j < 32; j += 8)
        dst[(size_t)(n0 + ty + j) * KK + k0 + tx] = __float2half(t[tx][ty + j]);
}

__global__ __launch_bounds__(256) void prep_kernel(
    const float* __restrict__ x,
    __half2* __restrict__ xhi2, __half2* __restrict__ xlo2,
    const float* __restrict__ Wq, const float* __restrict__ Wk,
    const float* __restrict__ Wv, const float* __restrict__ Wo,
    __half* __restrict__ wq, __half* __restrict__ wk,
    __half* __restrict__ wv, __half* __restrict__ wo,
    float2* __restrict__ ropet)
{
    __shared__ float t[32][33];
    const int bid = blockIdx.x;
    const int tid = threadIdx.x;

    if (bid < 512) {
        int i = bid * 256 + tid;
        int s = i >> 6, p = i & 63;
        float e   = (float)(2 * p) * (1.0f / 128.0f);
        float inv = 1.0f / powf(10000.0f, e);
        float sn, c;
        sincosf((float)s * inv, &sn, &c);
        ropet[i] = make_float2(c, sn);
    } else if (bid < 16896) {
        int i = (bid - 512) * 256 + tid;
        float2 v = ((const float2*)x)[i];
        __half hx = __float2half(v.x);
        __half hy = __float2half(v.y);
        xhi2[i] = __halves2half2(hx, hy);
        xlo2[i] = __halves2half2(__float2half(v.x - __half2float(hx)),
                                 __float2half(v.y - __half2float(hy)));
    } else {
        int r = bid - 16896;
        int tx = tid & 31, ty = tid >> 5;
        if (r < 4096)
            transpose_tile_h(Wq, wq, NQ,  r & 63, r >> 6, t, tx, ty);
        else if (r < 5120)
            transpose_tile_h(Wk, wk, NKV, (r - 4096) & 15, (r - 4096) >> 4, t, tx, ty);
        else if (r < 6144)
            transpose_tile_h(Wv, wv, NKV, (r - 5120) & 15, (r - 5120) >> 4, t, tx, ty);
        else
            transpose_tile_h(Wo, wo, NQ,  (r - 6144) & 63, (r - 6144) >> 6, t, tx, ty);
    }
}

// ---------------------------------------------------------------------------
// Flash attention: S = Qhi·K + Qlo·K (fp16 x2), P·V fp16. Causal, GQA 4:1.
// LPT 1-D grid. 3-stage KV ring; epilogue writes single fp16.
// ---------------------------------------------------------------------------
#define AP      272
#define QTB     (128 * AP)
#define KVTB    (64 * AP)
#define KVB     (2 * QTB)
#define KVSTG   (2 * KVTB)
#define ATTN_SMEM (2 * QTB + 3 * KVSTG)   // 174080

__device__ __forceinline__ void load_kv_tile(uint32_t sb, uint32_t stg,
    const __half* kf, const __half* vf, int k0, int tid)
{
#pragma unroll
    for (int t = 0; t < 8; t++) {
        int i  = tid + t * 256;
        int m  = i >> 10;
        int w  = i & 1023;
        int r  = w >> 4;
        int sg = w & 15;
        const __half* src = m ? vf : kf;
        cp16(sb + stg + (uint32_t)m * KVTB + (uint32_t)(r * AP + sg * 16),
             src + (size_t)(k0 + r) * NKV + sg * 8);
    }
}

__global__ __launch_bounds__(256) void attn_mma(
    const __half* __restrict__ qhi, const __half* __restrict__ qlo,
    const __half* __restrict__ kf, const __half* __restrict__ vf,
    __half* __restrict__ oa)
{
    extern __shared__ char sm[];
    const uint32_t sb = smem_u32(sm);

    const int bid = blockIdx.x;
    const int qt  = (SS / 128 - 1) - (bid >> 5);
    const int hb  = bid & 31;
    const int h   = hb & 15;
    const int b   = hb >> 4;
    const int kvh = h >> 2;
    const int q0  = qt * 128;

    const int tid  = threadIdx.x;
    const int lane = tid & 31;
    const int wid  = tid >> 5;
    const int wq0  = wid * 16;
    const int gr   = lane >> 2;

    const __half* qhb = qhi + ((size_t)b * SS + q0) * NQ + h * HDIM;
    const __half* qlb = qlo + ((size_t)b * SS + q0) * NQ + h * HDIM;
    const __half* kfb = kf + (size_t)b * SS * NKV + kvh * HDIM;
    const __half* vfb = vf + (size_t)b * SS * NKV + kvh * HDIM;

    const int ntiles = 2 * qt + 2;

#pragma unroll
    for (int t = 0; t < 16; t++) {
        int i   = tid + t * 256;
        int hl  = i >> 11;
        int w   = i & 2047;
        int r   = w >> 4;
        int sg  = w & 15;
        const __half* src = hl ? qlb : qhb;
        cp16(sb + (uint32_t)hl * QTB + (uint32_t)(r * AP + sg * 16),
             src + (size_t)r * NQ + sg * 8);
    }
    load_kv_tile(sb, KVB, kfb, vfb, 0, tid);
    CP_COMMIT();
    load_kv_tile(sb, KVB + KVSTG, kfb, vfb, 64, tid);
    CP_COMMIT();

    float oacc[16][4];
#pragma unroll
    for (int j = 0; j < 16; j++)
#pragma unroll
        for (int e = 0; e < 4; e++) oacc[j][e] = 0.0f;
    float mA = -1e30f, mB = -1e30f, lA = 0.0f, lB = 0.0f;

    const float scale = 0.08838834764831845f;
    const int rAg = q0 + wq0 + gr;
    const int rBg = rAg + 8;

#pragma unroll 1
    for (int t = 0; t < ntiles; t++) {
        if (t + 2 < ntiles) {
            load_kv_tile(sb, KVB + (uint32_t)((t + 2) % 3) * KVSTG,
                         kfb, vfb, (t + 2) * 64, tid);
            CP_COMMIT();
            CP_WAIT(2);
        } else if (t + 1 < ntiles) {
            CP_WAIT(1);
        } else {
            CP_WAIT(0);
        }
        __syncthreads();

        const uint32_t kv = sb + KVB + (uint32_t)(t % 3) * KVSTG;

        // ---- S = Q @ K^T (fp16 x2) ----
        float sacc[8][4];
#pragma unroll
        for (int j = 0; j < 8; j++)
#pragma unroll
            for (int e = 0; e < 4; e++) sacc[j][e] = 0.0f;

        const uint32_t aB = sb + (uint32_t)wq0 * AP;
#pragma unroll
        for (int c = 0; c < 8; c++) {
            const uint32_t ao = (uint32_t)((lane & 15) * AP
                              + (c * 16 + ((lane >> 4) << 3)) * 2);
            uint32_t ah0, ah1, ah2, ah3, al0, al1, al2, al3;
            ldm_x4(ah0, ah1, ah2, ah3, aB + ao);
            ldm_x4(al0, al1, al2, al3, aB + QTB + ao);
#pragma unroll
            for (int g = 0; g < 4; g++) {
                const uint32_t bo = (uint32_t)((g * 16 + ((lane >> 4) << 3) + (lane & 7)) * AP
                                  + (c * 16 + ((lane >> 3) & 1) * 8) * 2);
                uint32_t bh0, bh1, bh2, bh3;
                ldm_x4(bh0, bh1, bh2, bh3, kv + bo);
                mma16816h(sacc[2 * g],     ah0, ah1, ah2, ah3, bh0, bh1);
                mma16816h(sacc[2 * g + 1], ah0, ah1, ah2, ah3, bh2, bh3);
                mma16816h(sacc[2 * g],     al0, al1, al2, al3, bh0, bh1);
                mma16816h(sacc[2 * g + 1], al0, al1, al2, al3, bh2, bh3);
            }
        }

#pragma unroll
        for (int j = 0; j < 8; j++)
#pragma unroll
            for (int e = 0; e < 4; e++) sacc[j][e] *= scale;

        if (t >= 2 * qt) {
#pragma unroll
            for (int j = 0; j < 8; j++) {
                int col = t * 64 + j * 8 + 2 * (lane & 3);
                if (col     > rAg) sacc[j][0] = -1e30f;
                if (col + 1 > rAg) sacc[j][1] = -1e30f;
                if (col     > rBg) sacc[j][2] = -1e30f;
                if (col + 1 > rBg) sacc[j][3] = -1e30f;
            }
        }

        // ---- online softmax ----
        float mxA = -1e30f, mxB = -1e30f;
#pragma unroll
        for (int j = 0; j < 8; j++) {
            mxA = fmaxf(mxA, fmaxf(sacc[j][0], sacc[j][1]));
            mxB = fmaxf(mxB, fmaxf(sacc[j][2], sacc[j][3]));
        }
        mxA = fmaxf(mxA, __shfl_xor_sync(0xffffffffu, mxA, 1));
        mxA = fmaxf(mxA, __shfl_xor_sync(0xffffffffu, mxA, 2));
        mxB = fmaxf(mxB, __shfl_xor_sync(0xffffffffu, mxB, 1));
        mxB = fmaxf(mxB, __shfl_xor_sync(0xffffffffu, mxB, 2));

        float mnA = fmaxf(mA, mxA), mnB = fmaxf(mB, mxB);
        float facA = __expf(mA - mnA), facB = __expf(mB - mnB);
        float sA = 0.0f, sB = 0.0f;
#pragma unroll
        for (int j = 0; j < 8; j++) {
            float p0 = __expf(sacc[j][0] - mnA);
            float p1 = __expf(sacc[j][1] - mnA);
            float p2 = __expf(sacc[j][2] - mnB);
            float p3 = __expf(sacc[j][3] - mnB);
            sacc[j][0] = p0; sacc[j][1] = p1; sacc[j][2] = p2; sacc[j][3] = p3;
            sA += p0 + p1; sB += p2 + p3;
        }
        sA += __shfl_xor_sync(0xffffffffu, sA, 1);
        sA += __shfl_xor_sync(0xffffffffu, sA, 2);
        sB += __shfl_xor_sync(0xffffffffu, sB, 1);
        sB += __shfl_xor_sync(0xffffffffu, sB, 2);
        lA = lA * facA + sA; lB = lB * facB + sB;
        mA = mnA; mB = mnB;
#pragma unroll
        for (int j = 0; j < 16; j++) {
            oacc[j][0] *= facA; oacc[j][1] *= facA;
            oacc[j][2] *= facB; oacc[j][3] *= facB;
        }

        // ---- O += P @ V (single fp16 pass) ----
#pragma unroll
        for (int kc = 0; kc < 4; kc++) {
            const int j0 = 2 * kc, j1 = 2 * kc + 1;
            uint32_t ph[4];
            ph[0] = pack_h2(sacc[j0][0], sacc[j0][1]);
            ph[1] = pack_h2(sacc[j0][2], sacc[j0][3]);
            ph[2] = pack_h2(sacc[j1][0], sacc[j1][1]);
            ph[3] = pack_h2(sacc[j1][2], sacc[j1][3]);
#pragma unroll
            for (int bn = 0; bn < 8; bn++) {
                const uint32_t rowsel =
                    (uint32_t)((kc * 16 + ((lane >> 4) << 3) + (lane & 7)) * AP
                             + (bn * 16 + ((lane >> 3) & 1) * 8) * 2);
                uint32_t r0, r1, r2, r3;
                ldm_x4_t(r0, r1, r2, r3, kv + KVTB + rowsel);
                mma16816h(oacc[2 * bn],     ph[0], ph[1], ph[2], ph[3], r0, r2);
                mma16816h(oacc[2 * bn + 1], ph[0], ph[1], ph[2], ph[3], r1, r3);
            }
        }
        __syncthreads();
    }

    const float invA = 1.0f / lA, invB = 1.0f / lB;
    const size_t rowA = ((size_t)b * SS + rAg) * NQ;
    const size_t rowB = ((size_t)b * SS + rBg) * NQ;
#pragma unroll
    for (int j = 0; j < 16; j++) {
        int col = h * HDIM + j * 8 + 2 * (lane & 3);
        *(__half2*)(oa + rowA + col) = __floats2half2_rn(oacc[j][0] * invA, oacc[j][1] * invA);
        *(__half2*)(oa + rowB + col) = __floats2half2_rn(oacc[j][2] * invB, oacc[j][3] * invB);
    }
}

// ---------------------------------------------------------------------------
extern "C" void kernel_launch(void* const* d_in, const int* in_sizes, int n_in,
                              void* d_out, int out_size)
{
    const float* x  = (const float*)d_in[0];
    const float* Wq = (const float*)d_in[2];
    const float* Wk = (const float*)d_in[3];
    const float* Wv = (const float*)d_in[4];
    const float* Wo = (const float*)d_in[5];
    float* out = (float*)d_out;

    __half *xhi, *xlo, *af, *qh, *ql, *kf, *vf;
    __half *wq, *wk, *wv, *wo;
    float2* rope;
    (void)cudaGetSymbolAddress((void**)&xhi, g_xhi);
    (void)cudaGetSymbolAddress((void**)&xlo, g_xlo);
    (void)cudaGetSymbolAddress((void**)&af, g_af);
    (void)cudaGetSymbolAddress((void**)&qh, g_qhi);
    (void)cudaGetSymbolAddress((void**)&ql, g_qlo);
    (void)cudaGetSymbolAddress((void**)&kf, g_kf);
    (void)cudaGetSymbolAddress((void**)&vf, g_vf);
    (void)cudaGetSymbolAddress((void**)&wq, g_wqT);
    (void)cudaGetSymbolAddress((void**)&wk, g_wkT);
    (void)cudaGetSymbolAddress((void**)&wv, g_wvT);
    (void)cudaGetSymbolAddress((void**)&wo, g_woT);
    (void)cudaGetSymbolAddress((void**)&rope, g_rope);

    (void)cudaFuncSetAttribute(gemm_qkv,
                               cudaFuncAttributeMaxDynamicSharedMemorySize, GEMM_DSMEM);
    (void)cudaFuncSetAttribute(gemm_oproj,
                               cudaFuncAttributeMaxDynamicSharedMemorySize, GEMM1_DSMEM);
    (void)cudaFuncSetAttribute(attn_mma,
                               cudaFuncAttributeMaxDynamicSharedMemorySize, ATTN_SMEM);

    // 1) merged prep
    prep_kernel<<<PREP_GRID, 256>>>(x,
                                    (__half2*)xhi, (__half2*)xlo,
                                    Wq, Wk, Wv, Wo,
                                    wq, wk, wv, wo, rope);

    // 2) fused QKV projection (fp16 x2)
    gemm_qkv<<<768, 256, GEMM_DSMEM>>>(xhi, xlo, wq, wk, wv,
                                       qh, ql, kf, vf, rope);

    // 3) attention (fp16 x2 S, fp16 PV); writes single-fp16 attention output
    attn_mma<<<(SS / 128) * NHQ * BB, 256, ATTN_SMEM>>>(qh, ql, kf, vf, af);

    // 4) output projection (fp16 x1) -> fp32 out
    gemm_oproj<<<dim3(NQ / 128, MM / 128), 256, GEMM1_DSMEM>>>(af, wo, out, NQ);
}

// round 13
// speedup vs baseline: 1.7568x; 1.1432x over previous
#include <cuda_runtime.h>
#include <cuda_bf16.h>
#include <cuda_fp16.h>
#include <math.h>
#include <stdint.h>

#define BB   2
#define SS   2048
#define DD   2048
#define NHQ  16
#define NKVH 4
#define HDIM 128
#define MM   (BB*SS)       // 4096
#define KK   2048
#define NQ   (NHQ*HDIM)    // 2048
#define NKV  (NKVH*HDIM)   // 512

// ---------------- scratch (device globals; no allocation allowed) ----------
__device__ __half g_xhi[(size_t)MM*KK],  g_xlo[(size_t)MM*KK];
__device__ __half g_af[(size_t)MM*NQ];                 // attention out, fp16 single
__device__ __half g_qhi[(size_t)MM*NQ],  g_qlo[(size_t)MM*NQ];
__device__ __half g_kf[(size_t)MM*NKV];                // K fp16 single (roped)
__device__ __half g_vf[(size_t)MM*NKV];                // V fp16 single
__device__ __half g_wqT[(size_t)NQ*KK];
__device__ __half g_wkT[(size_t)NKV*KK];
__device__ __half g_wvT[(size_t)NKV*KK];
__device__ __half g_woT[(size_t)NQ*KK];
__device__ float2 g_rope[(size_t)SS*64];               // (cos, sin)

// ---------------- PTX helpers ----------------------------------------------
__device__ __forceinline__ uint32_t smem_u32(const void* p) {
    uint32_t a;
    asm("{ .reg .u64 t; cvta.to.shared.u64 t, %1; cvt.u32.u64 %0, t; }"
        : "=r"(a) : "l"(p));
    return a;
}

__device__ __forceinline__ void cp16(uint32_t s, const void* g) {
    asm volatile("cp.async.cg.shared.global [%0], [%1], 16;" :: "r"(s), "l"(g));
}
#define CP_COMMIT() asm volatile("cp.async.commit_group;" ::: "memory")
#define CP_WAIT(n)  asm volatile("cp.async.wait_group %0;" :: "n"(n) : "memory")

__device__ __forceinline__ void ldm_x4(uint32_t& r0, uint32_t& r1,
                                       uint32_t& r2, uint32_t& r3, uint32_t a) {
    asm volatile("ldmatrix.sync.aligned.m8n8.x4.shared.b16 {%0,%1,%2,%3}, [%4];"
                 : "=r"(r0), "=r"(r1), "=r"(r2), "=r"(r3) : "r"(a));
}
__device__ __forceinline__ void ldm_x4_t(uint32_t& r0, uint32_t& r1,
                                         uint32_t& r2, uint32_t& r3, uint32_t a) {
    asm volatile("ldmatrix.sync.aligned.m8n8.x4.trans.shared.b16 {%0,%1,%2,%3}, [%4];"
                 : "=r"(r0), "=r"(r1), "=r"(r2), "=r"(r3) : "r"(a));
}

__device__ __forceinline__ void mma16816h(float* c,
    uint32_t a0, uint32_t a1, uint32_t a2, uint32_t a3, uint32_t b0, uint32_t b1)
{
    asm volatile(
        "mma.sync.aligned.m16n8k16.row.col.f32.f16.f16.f32 "
        "{%0,%1,%2,%3}, {%4,%5,%6,%7}, {%8,%9}, {%0,%1,%2,%3};"
        : "+f"(c[0]), "+f"(c[1]), "+f"(c[2]), "+f"(c[3])
        : "r"(a0), "r"(a1), "r"(a2), "r"(a3), "r"(b0), "r"(b1));
}

__device__ __forceinline__ uint32_t pack_h2(float x, float y) {
    __half2 t = __floats2half2_rn(x, y);
    return *reinterpret_cast<uint32_t*>(&t);
}

__device__ __forceinline__ void store_hilo_h(__half* hi, __half* lo,
                                             size_t off, float a, float b)
{
    __half ha = __float2half(a), hb = __float2half(b);
    *(__half2*)(hi + off) = __halves2half2(ha, hb);
    *(__half2*)(lo + off) = __halves2half2(
        __float2half(a - __half2float(ha)),
        __float2half(b - __half2float(hb)));
}

// ---------------------------------------------------------------------------
// GEMM machinery. BK=32, pitch 80 B, 2-stage cp.async.
//   x2 variant: A hi/lo + B single (stage = 3 tiles)
//   x1 variant: A single + B single (stage = 2 tiles)
// ---------------------------------------------------------------------------
#define BK        32
#define ROWB      80
#define TILEB     (128 * ROWB)
#define OFF_AHI   0
#define OFF_ALO   (TILEB)
#define OFF_B     (2 * TILEB)
#define STAGEB    (3 * TILEB)          // 30720
#define GEMM_DSMEM (2 * STAGEB)        // 61440
#define OFF_B1    (TILEB)
#define STAGEB1   (2 * TILEB)          // 20480
#define GEMM1_DSMEM (2 * STAGEB1)      // 40960
#define NCHUNK    (KK / BK)            // 64

__device__ __forceinline__ void load_stage(uint32_t sBase,
    const __half* Ahi, const __half* Alo, const __half* Bs,
    int row0, int col0, int k0, int tid)
{
#pragma unroll
    for (int t = 0; t < 6; t++) {
        int i    = tid + t * 256;
        int tile = i >> 9;
        int w    = i & 511;
        int r    = w >> 2;
        int seg  = w & 3;
        const __half* src = (tile == 0) ? Ahi : (tile == 1) ? Alo : Bs;
        int rb = (tile < 2) ? row0 : col0;
        cp16(sBase + tile * TILEB + r * ROWB + seg * 16,
             src + (size_t)(rb + r) * KK + k0 + seg * 8);
    }
}

__device__ __forceinline__ void load_stage1(uint32_t sBase,
    const __half* As, const __half* Bs,
    int row0, int col0, int k0, int tid)
{
#pragma unroll
    for (int t = 0; t < 4; t++) {
        int i    = tid + t * 256;
        int tile = i >> 9;
        int w    = i & 511;
        int r    = w >> 2;
        int seg  = w & 3;
        const __half* src = (tile == 0) ? As : Bs;
        int rb = (tile == 0) ? row0 : col0;
        cp16(sBase + tile * TILEB + r * ROWB + seg * 16,
             src + (size_t)(rb + r) * KK + k0 + seg * 8);
    }
}

__device__ __forceinline__ void gemm_mainloop(uint32_t sBase,
    const __half* Ahi, const __half* Alo, const __half* Bs,
    int row0, int col0, int tid, int lane, int wr, int wc,
    float acc[4][4][4])
{
    load_stage(sBase, Ahi, Alo, Bs, row0, col0, 0, tid);
    CP_COMMIT();

#pragma unroll 1
    for (int c = 0; c < NCHUNK; c++) {
        const uint32_t st = sBase + (uint32_t)(c & 1) * STAGEB;
        if (c + 1 < NCHUNK) {
            load_stage(sBase + (uint32_t)((c + 1) & 1) * STAGEB,
                       Ahi, Alo, Bs, row0, col0, (c + 1) * BK, tid);
            CP_COMMIT();
            CP_WAIT(1);
        } else {
            CP_WAIT(0);
        }
        __syncthreads();

        const uint32_t aHiW = st + OFF_AHI + (uint32_t)(wr * 64) * ROWB;
        const uint32_t aLoW = st + OFF_ALO + (uint32_t)(wr * 64) * ROWB;
        const uint32_t bW   = st + OFF_B   + (uint32_t)(wc * 32) * ROWB;

#pragma unroll
        for (int ks = 0; ks < 2; ks++) {
            const uint32_t aoff = (uint32_t)((lane & 15) * ROWB
                                + (ks * 16 + ((lane >> 4) << 3)) * 2);
            uint32_t AH[4][4], AL[4][4];
#pragma unroll
            for (int am = 0; am < 4; am++) {
                ldm_x4(AH[am][0], AH[am][1], AH[am][2], AH[am][3],
                       aHiW + (uint32_t)(am * 16) * ROWB + aoff);
                ldm_x4(AL[am][0], AL[am][1], AL[am][2], AL[am][3],
                       aLoW + (uint32_t)(am * 16) * ROWB + aoff);
            }
            const uint32_t boff = (uint32_t)((((lane >> 4) << 3) + (lane & 7)) * ROWB
                                + (ks * 16 + ((lane >> 3) & 1) * 8) * 2);
            uint32_t Bx[2][4];
#pragma unroll
            for (int bn = 0; bn < 2; bn++)
                ldm_x4(Bx[bn][0], Bx[bn][1], Bx[bn][2], Bx[bn][3],
                       bW + (uint32_t)(bn * 16) * ROWB + boff);
#pragma unroll
            for (int am = 0; am < 4; am++)
#pragma unroll
                for (int an = 0; an < 4; an++) {
                    uint32_t b0 = Bx[an >> 1][(an & 1) * 2];
                    uint32_t b1 = Bx[an >> 1][(an & 1) * 2 + 1];
                    mma16816h(acc[am][an], AH[am][0], AH[am][1], AH[am][2], AH[am][3], b0, b1);
                    mma16816h(acc[am][an], AL[am][0], AL[am][1], AL[am][2], AL[am][3], b0, b1);
                }
        }
        __syncthreads();
    }
}

__device__ __forceinline__ void gemm_mainloop_x1(uint32_t sBase,
    const __half* As, const __half* Bs,
    int row0, int col0, int tid, int lane, int wr, int wc,
    float acc[4][4][4])
{
    load_stage1(sBase, As, Bs, row0, col0, 0, tid);
    CP_COMMIT();

#pragma unroll 1
    for (int c = 0; c < NCHUNK; c++) {
        const uint32_t st = sBase + (uint32_t)(c & 1) * STAGEB1;
        if (c + 1 < NCHUNK) {
            load_stage1(sBase + (uint32_t)((c + 1) & 1) * STAGEB1,
                        As, Bs, row0, col0, (c + 1) * BK, tid);
            CP_COMMIT();
            CP_WAIT(1);
        } else {
            CP_WAIT(0);
        }
        __syncthreads();

        const uint32_t aW = st + (uint32_t)(wr * 64) * ROWB;
        const uint32_t bW = st + OFF_B1 + (uint32_t)(wc * 32) * ROWB;

#pragma unroll
        for (int ks = 0; ks < 2; ks++) {
            const uint32_t aoff = (uint32_t)((lane & 15) * ROWB
                                + (ks * 16 + ((lane >> 4) << 3)) * 2);
            uint32_t A[4][4];
#pragma unroll
            for (int am = 0; am < 4; am++)
                ldm_x4(A[am][0], A[am][1], A[am][2], A[am][3],
                       aW + (uint32_t)(am * 16) * ROWB + aoff);
            const uint32_t boff = (uint32_t)((((lane >> 4) << 3) + (lane & 7)) * ROWB
                                + (ks * 16 + ((lane >> 3) & 1) * 8) * 2);
            uint32_t Bx[2][4];
#pragma unroll
            for (int bn = 0; bn < 2; bn++)
                ldm_x4(Bx[bn][0], Bx[bn][1], Bx[bn][2], Bx[bn][3],
                       bW + (uint32_t)(bn * 16) * ROWB + boff);
#pragma unroll
            for (int am = 0; am < 4; am++)
#pragma unroll
                for (int an = 0; an < 4; an++)
                    mma16816h(acc[am][an], A[am][0], A[am][1], A[am][2], A[am][3],
                              Bx[an >> 1][(an & 1) * 2], Bx[an >> 1][(an & 1) * 2 + 1]);
        }
        __syncthreads();
    }
}

// ---------------------------------------------------------------------------
// Fused QKV projection: 1-D grid of 768 CTAs.
//   [0,512):   Q -> x2 mainloop, rope + fp16 hi/lo out
//   [512,640): K -> x1 mainloop (xhi only), rope + fp16 single out
//   [640,768): V -> x1 mainloop (xhi only), fp16 single out
// ---------------------------------------------------------------------------
__global__ __launch_bounds__(256) void gemm_qkv(
    const __half* __restrict__ xhi, const __half* __restrict__ xlo,
    const __half* __restrict__ wq, const __half* __restrict__ wk,
    const __half* __restrict__ wv,
    __half* __restrict__ qh, __half* __restrict__ ql,
    __half* __restrict__ kf, __half* __restrict__ vf,
    const float2* __restrict__ rope)
{
    extern __shared__ char dsm[];
    const uint32_t sBase = smem_u32(dsm);

    const int tid  = threadIdx.x;
    const int lane = tid & 31;
    const int wid  = tid >> 5;
    const int wr   = wid >> 2;
    const int wc   = wid & 3;

    const int bid = blockIdx.x;
    const __half* Bs;
    int row0, col0, N, mode;   // 0=Q rope hi/lo, 1=K rope single, 2=V single
    if (bid < 512) {
        row0 = (bid >> 4) * 128; col0 = (bid & 15) * 128;
        Bs = wq; N = NQ; mode = 0;
    } else if (bid < 640) {
        int i = bid - 512;
        row0 = (i >> 2) * 128; col0 = (i & 3) * 128;
        Bs = wk; N = NKV; mode = 1;
    } else {
        int i = bid - 640;
        row0 = (i >> 2) * 128; col0 = (i & 3) * 128;
        Bs = wv; N = NKV; mode = 2;
    }

    float acc[4][4][4];
#pragma unroll
    for (int i = 0; i < 4; i++)
#pragma unroll
        for (int j = 0; j < 4; j++)
#pragma unroll
            for (int l = 0; l < 4; l++) acc[i][j][l] = 0.0f;

    if (mode == 0)
        gemm_mainloop(sBase, xhi, xlo, Bs, row0, col0, tid, lane, wr, wc, acc);
    else
        gemm_mainloop_x1(sBase, xhi, Bs, row0, col0, tid, lane, wr, wc, acc);

    const int rbase = row0 + wr * 64;
    const int cbase = col0 + wc * 32;
#pragma unroll
    for (int am = 0; am < 4; am++)
#pragma unroll
        for (int an = 0; an < 4; an++) {
            float* cf = acc[am][an];
            int r  = rbase + am * 16 + (lane >> 2);
            int cc = cbase + an * 8 + (lane & 3) * 2;
            if (mode == 2) {
                *(__half2*)(vf + (size_t)r * N + cc)       = __floats2half2_rn(cf[0], cf[1]);
                *(__half2*)(vf + (size_t)(r + 8) * N + cc) = __floats2half2_rn(cf[2], cf[3]);
            } else {
                int p = (cc & 127) >> 1;
                float2 cs0 = rope[(size_t)(r & (SS - 1)) * 64 + p];
                float2 cs1 = rope[(size_t)((r + 8) & (SS - 1)) * 64 + p];
                float o0 = cf[0] * cs0.x - cf[1] * cs0.y;
                float o1 = cf[0] * cs0.y + cf[1] * cs0.x;
                float o2 = cf[2] * cs1.x - cf[3] * cs1.y;
                float o3 = cf[2] * cs1.y + cf[3] * cs1.x;
                if (mode == 0) {
                    store_hilo_h(qh, ql, (size_t)r * N + cc,       o0, o1);
                    store_hilo_h(qh, ql, (size_t)(r + 8) * N + cc, o2, o3);
                } else {
                    *(__half2*)(kf + (size_t)r * N + cc)       = __floats2half2_rn(o0, o1);
                    *(__half2*)(kf + (size_t)(r + 8) * N + cc) = __floats2half2_rn(o2, o3);
                }
            }
        }
}

// ---------------------------------------------------------------------------
// O-projection GEMM: A single fp16, fp32 C output
// ---------------------------------------------------------------------------
__global__ __launch_bounds__(256) void gemm_oproj(
    const __half* __restrict__ As, const __half* __restrict__ Bs,
    float* __restrict__ C, int N)
{
    extern __shared__ char dsm[];
    const uint32_t sBase = smem_u32(dsm);

    const int tid  = threadIdx.x;
    const int lane = tid & 31;
    const int wid  = tid >> 5;
    const int wr   = wid >> 2;
    const int wc   = wid & 3;
    const int row0 = blockIdx.y * 128;
    const int col0 = blockIdx.x * 128;

    float acc[4][4][4];
#pragma unroll
    for (int i = 0; i < 4; i++)
#pragma unroll
        for (int j = 0; j < 4; j++)
#pragma unroll
            for (int l = 0; l < 4; l++) acc[i][j][l] = 0.0f;

    gemm_mainloop_x1(sBase, As, Bs, row0, col0, tid, lane, wr, wc, acc);

    const int rbase = row0 + wr * 64;
    const int cbase = col0 + wc * 32;
#pragma unroll
    for (int am = 0; am < 4; am++)
#pragma unroll
        for (int an = 0; an < 4; an++) {
            float* cf = acc[am][an];
            int r  = rbase + am * 16 + (lane >> 2);
            int cc = cbase + an * 8 + (lane & 3) * 2;
            *(float2*)(C + (size_t)r * N + cc)       = make_float2(cf[0], cf[1]);
            *(float2*)(C + (size_t)(r + 8) * N + cc) = make_float2(cf[2], cf[3]);
        }
}

// ---------------------------------------------------------------------------
// Merged prep: rope table + x fp16 hi/lo split + 4 weight transposes (fp16)
// ---------------------------------------------------------------------------
#define PREP_GRID 27136

__device__ __forceinline__ void transpose_tile_h(
    const float* __restrict__ src, __half* __restrict__ dst,
    int N, int bx, int by, float (*t)[33], int tx, int ty)
{
    int k0 = by * 32, n0 = bx * 32;
#pragma unroll
    for (int j = 0; j < 32; j += 8)
        t[ty + j][tx] = src[(size_t)(k0 + ty + j) * N + n0 + tx];
    __syncthreads();
#pragma unroll
    for (int j = 0; j < 32; j += 8)
        dst[(size_t)(n0 + ty + j) * KK + k0 + tx] = __float2half(t[tx][ty + j]);
}

__global__ __launch_bounds__(256) void prep_kernel(
    const float* __restrict__ x,
    __half2* __restrict__ xhi2, __half2* __restrict__ xlo2,
    const float* __restrict__ Wq, const float* __restrict__ Wk,
    const float* __restrict__ Wv, const float* __restrict__ Wo,
    __half* __restrict__ wq, __half* __restrict__ wk,
    __half* __restrict__ wv, __half* __restrict__ wo,
    float2* __restrict__ ropet)
{
    __shared__ float t[32][33];
    const int bid = blockIdx.x;
    const int tid = threadIdx.x;

    if (bid < 512) {
        int i = bid * 256 + tid;
        int s = i >> 6, p = i & 63;
        float e   = (float)(2 * p) * (1.0f / 128.0f);
        float inv = 1.0f / powf(10000.0f, e);
        float sn, c;
        sincosf((float)s * inv, &sn, &c);
        ropet[i] = make_float2(c, sn);
    } else if (bid < 16896) {
        int i = (bid - 512) * 256 + tid;
        float2 v = ((const float2*)x)[i];
        __half hx = __float2half(v.x);
        __half hy = __float2half(v.y);
        xhi2[i] = __halves2half2(hx, hy);
        xlo2[i] = __halves2half2(__float2half(v.x - __half2float(hx)),
                                 __float2half(v.y - __half2float(hy)));
    } else {
        int r = bid - 16896;
        int tx = tid & 31, ty = tid >> 5;
        if (r < 4096)
            transpose_tile_h(Wq, wq, NQ,  r & 63, r >> 6, t, tx, ty);
        else if (r < 5120)
            transpose_tile_h(Wk, wk, NKV, (r - 4096) & 15, (r - 4096) >> 4, t, tx, ty);
        else if (r < 6144)
            transpose_tile_h(Wv, wv, NKV, (r - 5120) & 15, (r - 5120) >> 4, t, tx, ty);
        else
            transpose_tile_h(Wo, wo, NQ,  (r - 6144) & 63, (r - 6144) >> 6, t, tx, ty);
    }
}

// ---------------------------------------------------------------------------
// Flash attention: S = Qhi·K + Qlo·K (fp16 x2), P·V fp16. Causal, GQA 4:1.
// LPT 1-D grid. 3-stage KV ring; epilogue writes single fp16.
// ---------------------------------------------------------------------------
#define AP      272
#define QTB     (128 * AP)
#define KVTB    (64 * AP)
#define KVB     (2 * QTB)
#define KVSTG   (2 * KVTB)
#define ATTN_SMEM (2 * QTB + 3 * KVSTG)   // 174080

__device__ __forceinline__ void load_kv_tile(uint32_t sb, uint32_t stg,
    const __half* kf, const __half* vf, int k0, int tid)
{
#pragma unroll
    for (int t = 0; t < 8; t++) {
        int i  = tid + t * 256;
        int m  = i >> 10;
        int w  = i & 1023;
        int r  = w >> 4;
        int sg = w & 15;
        const __half* src = m ? vf : kf;
        cp16(sb + stg + (uint32_t)m * KVTB + (uint32_t)(r * AP + sg * 16),
             src + (size_t)(k0 + r) * NKV + sg * 8);
    }
}

__global__ __launch_bounds__(256) void attn_mma(
    const __half* __restrict__ qhi, const __half* __restrict__ qlo,
    const __half* __restrict__ kf, const __half* __restrict__ vf,
    __half* __restrict__ oa)
{
    extern __shared__ char sm[];
    const uint32_t sb = smem_u32(sm);

    const int bid = blockIdx.x;
    const int qt  = (SS / 128 - 1) - (bid >> 5);
    const int hb  = bid & 31;
    const int h   = hb & 15;
    const int b   = hb >> 4;
    const int kvh = h >> 2;
    const int q0  = qt * 128;

    const int tid  = threadIdx.x;
    const int lane = tid & 31;
    const int wid  = tid >> 5;
    const int wq0  = wid * 16;
    const int gr   = lane >> 2;

    const __half* qhb = qhi + ((size_t)b * SS + q0) * NQ + h * HDIM;
    const __half* qlb = qlo + ((size_t)b * SS + q0) * NQ + h * HDIM;
    const __half* kfb = kf + (size_t)b * SS * NKV + kvh * HDIM;
    const __half* vfb = vf + (size_t)b * SS * NKV + kvh * HDIM;

    const int ntiles = 2 * qt + 2;

#pragma unroll
    for (int t = 0; t < 16; t++) {
        int i   = tid + t * 256;
        int hl  = i >> 11;
        int w   = i & 2047;
        int r   = w >> 4;
        int sg  = w & 15;
        const __half* src = hl ? qlb : qhb;
        cp16(sb + (uint32_t)hl * QTB + (uint32_t)(r * AP + sg * 16),
             src + (size_t)r * NQ + sg * 8);
    }
    load_kv_tile(sb, KVB, kfb, vfb, 0, tid);
    CP_COMMIT();
    load_kv_tile(sb, KVB + KVSTG, kfb, vfb, 64, tid);
    CP_COMMIT();

    float oacc[16][4];
#pragma unroll
    for (int j = 0; j < 16; j++)
#pragma unroll
        for (int e = 0; e < 4; e++) oacc[j][e] = 0.0f;
    float mA = -1e30f, mB = -1e30f, lA = 0.0f, lB = 0.0f;

    const float scale = 0.08838834764831845f;
    const int rAg = q0 + wq0 + gr;
    const int rBg = rAg + 8;

#pragma unroll 1
    for (int t = 0; t < ntiles; t++) {
        if (t + 2 < ntiles) {
            load_kv_tile(sb, KVB + (uint32_t)((t + 2) % 3) * KVSTG,
                         kfb, vfb, (t + 2) * 64, tid);
            CP_COMMIT();
            CP_WAIT(2);
        } else if (t + 1 < ntiles) {
            CP_WAIT(1);
        } else {
            CP_WAIT(0);
        }
        __syncthreads();

        const uint32_t kv = sb + KVB + (uint32_t)(t % 3) * KVSTG;

        // ---- S = Q @ K^T (fp16 x2) ----
        float sacc[8][4];
#pragma unroll
        for (int j = 0; j < 8; j++)
#pragma unroll
            for (int e = 0; e < 4; e++) sacc[j][e] = 0.0f;

        const uint32_t aB = sb + (uint32_t)wq0 * AP;
#pragma unroll
        for (int c = 0; c < 8; c++) {
            const uint32_t ao = (uint32_t)((lane & 15) * AP
                              + (c * 16 + ((lane >> 4) << 3)) * 2);
            uint32_t ah0, ah1, ah2, ah3, al0, al1, al2, al3;
            ldm_x4(ah0, ah1, ah2, ah3, aB + ao);
            ldm_x4(al0, al1, al2, al3, aB + QTB + ao);
#pragma unroll
            for (int g = 0; g < 4; g++) {
                const uint32_t bo = (uint32_t)((g * 16 + ((lane >> 4) << 3) + (lane & 7)) * AP
                                  + (c * 16 + ((lane >> 3) & 1) * 8) * 2);
                uint32_t bh0, bh1, bh2, bh3;
                ldm_x4(bh0, bh1, bh2, bh3, kv + bo);
                mma16816h(sacc[2 * g],     ah0, ah1, ah2, ah3, bh0, bh1);
                mma16816h(sacc[2 * g + 1], ah0, ah1, ah2, ah3, bh2, bh3);
                mma16816h(sacc[2 * g],     al0, al1, al2, al3, bh0, bh1);
                mma16816h(sacc[2 * g + 1], al0, al1, al2, al3, bh2, bh3);
            }
        }

#pragma unroll
        for (int j = 0; j < 8; j++)
#pragma unroll
            for (int e = 0; e < 4; e++) sacc[j][e] *= scale;

        if (t >= 2 * qt) {
#pragma unroll
            for (int j = 0; j < 8; j++) {
                int col = t * 64 + j * 8 + 2 * (lane & 3);
                if (col     > rAg) sacc[j][0] = -1e30f;
                if (col + 1 > rAg) sacc[j][1] = -1e30f;
                if (col     > rBg) sacc[j][2] = -1e30f;
                if (col + 1 > rBg) sacc[j][3] = -1e30f;
            }
        }

        // ---- online softmax ----
        float mxA = -1e30f, mxB = -1e30f;
#pragma unroll
        for (int j = 0; j < 8; j++) {
            mxA = fmaxf(mxA, fmaxf(sacc[j][0], sacc[j][1]));
            mxB = fmaxf(mxB, fmaxf(sacc[j][2], sacc[j][3]));
        }
        mxA = fmaxf(mxA, __shfl_xor_sync(0xffffffffu, mxA, 1));
        mxA = fmaxf(mxA, __shfl_xor_sync(0xffffffffu, mxA, 2));
        mxB = fmaxf(mxB, __shfl_xor_sync(0xffffffffu, mxB, 1));
        mxB = fmaxf(mxB, __shfl_xor_sync(0xffffffffu, mxB, 2));

        float mnA = fmaxf(mA, mxA), mnB = fmaxf(mB, mxB);
        float facA = __expf(mA - mnA), facB = __expf(mB - mnB);
        float sA = 0.0f, sB = 0.0f;
#pragma unroll
        for (int j = 0; j < 8; j++) {
            float p0 = __expf(sacc[j][0] - mnA);
            float p1 = __expf(sacc[j][1] - mnA);
            float p2 = __expf(sacc[j][2] - mnB);
            float p3 = __expf(sacc[j][3] - mnB);
            sacc[j][0] = p0; sacc[j][1] = p1; sacc[j][2] = p2; sacc[j][3] = p3;
            sA += p0 + p1; sB += p2 + p3;
        }
        sA += __shfl_xor_sync(0xffffffffu, sA, 1);
        sA += __shfl_xor_sync(0xffffffffu, sA, 2);
        sB += __shfl_xor_sync(0xffffffffu, sB, 1);
        sB += __shfl_xor_sync(0xffffffffu, sB, 2);
        lA = lA * facA + sA; lB = lB * facB + sB;
        mA = mnA; mB = mnB;
#pragma unroll
        for (int j = 0; j < 16; j++) {
            oacc[j][0] *= facA; oacc[j][1] *= facA;
            oacc[j][2] *= facB; oacc[j][3] *= facB;
        }

        // ---- O += P @ V (single fp16 pass) ----
#pragma unroll
        for (int kc = 0; kc < 4; kc++) {
            const int j0 = 2 * kc, j1 = 2 * kc + 1;
            uint32_t ph[4];
            ph[0] = pack_h2(sacc[j0][0], sacc[j0][1]);
            ph[1] = pack_h2(sacc[j0][2], sacc[j0][3]);
            ph[2] = pack_h2(sacc[j1][0], sacc[j1][1]);
            ph[3] = pack_h2(sacc[j1][2], sacc[j1][3]);
#pragma unroll
            for (int bn = 0; bn < 8; bn++) {
                const uint32_t rowsel =
                    (uint32_t)((kc * 16 + ((lane >> 4) << 3) + (lane & 7)) * AP
                             + (bn * 16 + ((lane >> 3) & 1) * 8) * 2);
                uint32_t r0, r1, r2, r3;
                ldm_x4_t(r0, r1, r2, r3, kv + KVTB + rowsel);
                mma16816h(oacc[2 * bn],     ph[0], ph[1], ph[2], ph[3], r0, r2);
                mma16816h(oacc[2 * bn + 1], ph[0], ph[1], ph[2], ph[3], r1, r3);
            }
        }
        __syncthreads();
    }

    const float invA = 1.0f / lA, invB = 1.0f / lB;
    const size_t rowA = ((size_t)b * SS + rAg) * NQ;
    const size_t rowB = ((size_t)b * SS + rBg) * NQ;
#pragma unroll
    for (int j = 0; j < 16; j++) {
        int col = h * HDIM + j * 8 + 2 * (lane & 3);
        *(__half2*)(oa + rowA + col) = __floats2half2_rn(oacc[j][0] * invA, oacc[j][1] * invA);
        *(__half2*)(oa + rowB + col) = __floats2half2_rn(oacc[j][2] * invB, oacc[j][3] * invB);
    }
}

// ---------------------------------------------------------------------------
extern "C" void kernel_launch(void* const* d_in, const int* in_sizes, int n_in,
                              void* d_out, int out_size)
{
    const float* x  = (const float*)d_in[0];
    const float* Wq = (const float*)d_in[2];
    const float* Wk = (const float*)d_in[3];
    const float* Wv = (const float*)d_in[4];
    const float* Wo = (const float*)d_in[5];
    float* out = (float*)d_out;

    __half *xhi, *xlo, *af, *qh, *ql, *kf, *vf;
    __half *wq, *wk, *wv, *wo;
    float2* rope;
    (void)cudaGetSymbolAddress((void**)&xhi, g_xhi);
    (void)cudaGetSymbolAddress((void**)&xlo, g_xlo);
    (void)cudaGetSymbolAddress((void**)&af, g_af);
    (void)cudaGetSymbolAddress((void**)&qh, g_qhi);
    (void)cudaGetSymbolAddress((void**)&ql, g_qlo);
    (void)cudaGetSymbolAddress((void**)&kf, g_kf);
    (void)cudaGetSymbolAddress((void**)&vf, g_vf);
    (void)cudaGetSymbolAddress((void**)&wq, g_wqT);
    (void)cudaGetSymbolAddress((void**)&wk, g_wkT);
    (void)cudaGetSymbolAddress((void**)&wv, g_wvT);
    (void)cudaGetSymbolAddress((void**)&wo, g_woT);
    (void)cudaGetSymbolAddress((void**)&rope, g_rope);

    (void)cudaFuncSetAttribute(gemm_qkv,
                               cudaFuncAttributeMaxDynamicSharedMemorySize, GEMM_DSMEM);
    (void)cudaFuncSetAttribute(gemm_oproj,
                               cudaFuncAttributeMaxDynamicSharedMemorySize, GEMM1_DSMEM);
    (void)cudaFuncSetAttribute(attn_mma,
                               cudaFuncAttributeMaxDynamicSharedMemorySize, ATTN_SMEM);

    // 1) merged prep
    prep_kernel<<<PREP_GRID, 256>>>(x,
                                    (__half2*)xhi, (__half2*)xlo,
                                    Wq, Wk, Wv, Wo,
                                    wq, wk, wv, wo, rope);

    // 2) fused QKV projection (Q: fp16 x2; K,V: fp16 x1)
    gemm_qkv<<<768, 256, GEMM_DSMEM>>>(xhi, xlo, wq, wk, wv,
                                       qh, ql, kf, vf, rope);

    // 3) attention (fp16 x2 S, fp16 PV); writes single-fp16 attention output
    attn_mma<<<(SS / 128) * NHQ * BB, 256, ATTN_SMEM>>>(qh, ql, kf, vf, af);

    // 4) output projection (fp16 x1) -> fp32 out
    gemm_oproj<<<dim3(NQ / 128, MM / 128), 256, GEMM1_DSMEM>>>(af, wo, out, NQ);
}

// round 14
// speedup vs baseline: 1.8777x; 1.0688x over previous
#include <cuda_runtime.h>
#include <cuda_bf16.h>
#include <cuda_fp16.h>
#include <math.h>
#include <stdint.h>

#define BB   2
#define SS   2048
#define DD   2048
#define NHQ  16
#define NKVH 4
#define HDIM 128
#define MM   (BB*SS)       // 4096
#define KK   2048
#define NQ   (NHQ*HDIM)    // 2048
#define NKV  (NKVH*HDIM)   // 512

// ---------------- scratch (device globals; no allocation allowed) ----------
__device__ __half g_xhi[(size_t)MM*KK],  g_xlo[(size_t)MM*KK];
__device__ __half g_af[(size_t)MM*NQ];                 // attention out, fp16 single
__device__ __half g_qhi[(size_t)MM*NQ],  g_qlo[(size_t)MM*NQ];
__device__ __half g_kf[(size_t)MM*NKV];                // K fp16 single (roped)
__device__ __half g_vf[(size_t)MM*NKV];                // V fp16 single
__device__ __half g_wqT[(size_t)NQ*KK];
__device__ __half g_wkT[(size_t)NKV*KK];
__device__ __half g_wvT[(size_t)NKV*KK];
__device__ __half g_woT[(size_t)NQ*KK];
__device__ float2 g_rope[(size_t)SS*64];               // (cos, sin)

// ---------------- PTX helpers ----------------------------------------------
__device__ __forceinline__ uint32_t smem_u32(const void* p) {
    uint32_t a;
    asm("{ .reg .u64 t; cvta.to.shared.u64 t, %1; cvt.u32.u64 %0, t; }"
        : "=r"(a) : "l"(p));
    return a;
}

__device__ __forceinline__ void cp16(uint32_t s, const void* g) {
    asm volatile("cp.async.cg.shared.global [%0], [%1], 16;" :: "r"(s), "l"(g));
}
#define CP_COMMIT() asm volatile("cp.async.commit_group;" ::: "memory")
#define CP_WAIT(n)  asm volatile("cp.async.wait_group %0;" :: "n"(n) : "memory")

__device__ __forceinline__ void ldm_x4(uint32_t& r0, uint32_t& r1,
                                       uint32_t& r2, uint32_t& r3, uint32_t a) {
    asm volatile("ldmatrix.sync.aligned.m8n8.x4.shared.b16 {%0,%1,%2,%3}, [%4];"
                 : "=r"(r0), "=r"(r1), "=r"(r2), "=r"(r3) : "r"(a));
}
__device__ __forceinline__ void ldm_x4_t(uint32_t& r0, uint32_t& r1,
                                         uint32_t& r2, uint32_t& r3, uint32_t a) {
    asm volatile("ldmatrix.sync.aligned.m8n8.x4.trans.shared.b16 {%0,%1,%2,%3}, [%4];"
                 : "=r"(r0), "=r"(r1), "=r"(r2), "=r"(r3) : "r"(a));
}

__device__ __forceinline__ void mma16816h(float* c,
    uint32_t a0, uint32_t a1, uint32_t a2, uint32_t a3, uint32_t b0, uint32_t b1)
{
    asm volatile(
        "mma.sync.aligned.m16n8k16.row.col.f32.f16.f16.f32 "
        "{%0,%1,%2,%3}, {%4,%5,%6,%7}, {%8,%9}, {%0,%1,%2,%3};"
        : "+f"(c[0]), "+f"(c[1]), "+f"(c[2]), "+f"(c[3])
        : "r"(a0), "r"(a1), "r"(a2), "r"(a3), "r"(b0), "r"(b1));
}

__device__ __forceinline__ uint32_t pack_h2(float x, float y) {
    __half2 t = __floats2half2_rn(x, y);
    return *reinterpret_cast<uint32_t*>(&t);
}

__device__ __forceinline__ void store_hilo_h(__half* hi, __half* lo,
                                             size_t off, float a, float b)
{
    __half ha = __float2half(a), hb = __float2half(b);
    *(__half2*)(hi + off) = __halves2half2(ha, hb);
    *(__half2*)(lo + off) = __halves2half2(
        __float2half(a - __half2float(ha)),
        __float2half(b - __half2float(hb)));
}

// ---------------------------------------------------------------------------
// GEMM machinery. BK=64, pitch 144 B, 2-stage cp.async.
//   x2 variant: A hi/lo + B single (stage = 3 tiles)
//   x1 variant: A single + B single (stage = 2 tiles)
// ---------------------------------------------------------------------------
#define BK        64
#define ROWB      144                  // 64 halves (128 B) + 16 pad
#define TILEB     (128 * ROWB)         // 18432
#define OFF_AHI   0
#define OFF_ALO   (TILEB)
#define OFF_B     (2 * TILEB)
#define STAGEB    (3 * TILEB)          // 55296
#define GEMM_DSMEM (2 * STAGEB)        // 110592
#define OFF_B1    (TILEB)
#define STAGEB1   (2 * TILEB)          // 36864
#define GEMM1_DSMEM (2 * STAGEB1)      // 73728
#define NCHUNK    (KK / BK)            // 32

__device__ __forceinline__ void load_stage(uint32_t sBase,
    const __half* Ahi, const __half* Alo, const __half* Bs,
    int row0, int col0, int k0, int tid)
{
#pragma unroll
    for (int t = 0; t < 12; t++) {
        int i    = tid + t * 256;
        int tile = i >> 10;                // constant per unrolled t
        int w    = i & 1023;
        int r    = w >> 3;
        int sg   = w & 7;
        const __half* src = (tile == 0) ? Ahi : (tile == 1) ? Alo : Bs;
        int rb = (tile < 2) ? row0 : col0;
        cp16(sBase + tile * TILEB + r * ROWB + sg * 16,
             src + (size_t)(rb + r) * KK + k0 + sg * 8);
    }
}

__device__ __forceinline__ void load_stage1(uint32_t sBase,
    const __half* As, const __half* Bs,
    int row0, int col0, int k0, int tid)
{
#pragma unroll
    for (int t = 0; t < 8; t++) {
        int i    = tid + t * 256;
        int tile = i >> 10;                // constant per unrolled t
        int w    = i & 1023;
        int r    = w >> 3;
        int sg   = w & 7;
        const __half* src = (tile == 0) ? As : Bs;
        int rb = (tile == 0) ? row0 : col0;
        cp16(sBase + tile * TILEB + r * ROWB + sg * 16,
             src + (size_t)(rb + r) * KK + k0 + sg * 8);
    }
}

__device__ __forceinline__ void gemm_mainloop(uint32_t sBase,
    const __half* Ahi, const __half* Alo, const __half* Bs,
    int row0, int col0, int tid, int lane, int wr, int wc,
    float acc[4][4][4])
{
    load_stage(sBase, Ahi, Alo, Bs, row0, col0, 0, tid);
    CP_COMMIT();

#pragma unroll 1
    for (int c = 0; c < NCHUNK; c++) {
        const uint32_t st = sBase + (uint32_t)(c & 1) * STAGEB;
        if (c + 1 < NCHUNK) {
            load_stage(sBase + (uint32_t)((c + 1) & 1) * STAGEB,
                       Ahi, Alo, Bs, row0, col0, (c + 1) * BK, tid);
            CP_COMMIT();
            CP_WAIT(1);
        } else {
            CP_WAIT(0);
        }
        __syncthreads();

        const uint32_t aHiW = st + OFF_AHI + (uint32_t)(wr * 64) * ROWB;
        const uint32_t aLoW = st + OFF_ALO + (uint32_t)(wr * 64) * ROWB;
        const uint32_t bW   = st + OFF_B   + (uint32_t)(wc * 32) * ROWB;

#pragma unroll
        for (int ks = 0; ks < 4; ks++) {
            const uint32_t aoff = (uint32_t)((lane & 15) * ROWB
                                + (ks * 16 + ((lane >> 4) << 3)) * 2);
            uint32_t AH[4][4], AL[4][4];
#pragma unroll
            for (int am = 0; am < 4; am++) {
                ldm_x4(AH[am][0], AH[am][1], AH[am][2], AH[am][3],
                       aHiW + (uint32_t)(am * 16) * ROWB + aoff);
                ldm_x4(AL[am][0], AL[am][1], AL[am][2], AL[am][3],
                       aLoW + (uint32_t)(am * 16) * ROWB + aoff);
            }
            const uint32_t boff = (uint32_t)((((lane >> 4) << 3) + (lane & 7)) * ROWB
                                + (ks * 16 + ((lane >> 3) & 1) * 8) * 2);
            uint32_t Bx[2][4];
#pragma unroll
            for (int bn = 0; bn < 2; bn++)
                ldm_x4(Bx[bn][0], Bx[bn][1], Bx[bn][2], Bx[bn][3],
                       bW + (uint32_t)(bn * 16) * ROWB + boff);
#pragma unroll
            for (int am = 0; am < 4; am++)
#pragma unroll
                for (int an = 0; an < 4; an++) {
                    uint32_t b0 = Bx[an >> 1][(an & 1) * 2];
                    uint32_t b1 = Bx[an >> 1][(an & 1) * 2 + 1];
                    mma16816h(acc[am][an], AH[am][0], AH[am][1], AH[am][2], AH[am][3], b0, b1);
                    mma16816h(acc[am][an], AL[am][0], AL[am][1], AL[am][2], AL[am][3], b0, b1);
                }
        }
        __syncthreads();
    }
}

__device__ __forceinline__ void gemm_mainloop_x1(uint32_t sBase,
    const __half* As, const __half* Bs,
    int row0, int col0, int tid, int lane, int wr, int wc,
    float acc[4][4][4])
{
    load_stage1(sBase, As, Bs, row0, col0, 0, tid);
    CP_COMMIT();

#pragma unroll 1
    for (int c = 0; c < NCHUNK; c++) {
        const uint32_t st = sBase + (uint32_t)(c & 1) * STAGEB1;
        if (c + 1 < NCHUNK) {
            load_stage1(sBase + (uint32_t)((c + 1) & 1) * STAGEB1,
                        As, Bs, row0, col0, (c + 1) * BK, tid);
            CP_COMMIT();
            CP_WAIT(1);
        } else {
            CP_WAIT(0);
        }
        __syncthreads();

        const uint32_t aW = st + (uint32_t)(wr * 64) * ROWB;
        const uint32_t bW = st + OFF_B1 + (uint32_t)(wc * 32) * ROWB;

#pragma unroll
        for (int ks = 0; ks < 4; ks++) {
            const uint32_t aoff = (uint32_t)((lane & 15) * ROWB
                                + (ks * 16 + ((lane >> 4) << 3)) * 2);
            uint32_t A[4][4];
#pragma unroll
            for (int am = 0; am < 4; am++)
                ldm_x4(A[am][0], A[am][1], A[am][2], A[am][3],
                       aW + (uint32_t)(am * 16) * ROWB + aoff);
            const uint32_t boff = (uint32_t)((((lane >> 4) << 3) + (lane & 7)) * ROWB
                                + (ks * 16 + ((lane >> 3) & 1) * 8) * 2);
            uint32_t Bx[2][4];
#pragma unroll
            for (int bn = 0; bn < 2; bn++)
                ldm_x4(Bx[bn][0], Bx[bn][1], Bx[bn][2], Bx[bn][3],
                       bW + (uint32_t)(bn * 16) * ROWB + boff);
#pragma unroll
            for (int am = 0; am < 4; am++)
#pragma unroll
                for (int an = 0; an < 4; an++)
                    mma16816h(acc[am][an], A[am][0], A[am][1], A[am][2], A[am][3],
                              Bx[an >> 1][(an & 1) * 2], Bx[an >> 1][(an & 1) * 2 + 1]);
        }
        __syncthreads();
    }
}

// ---------------------------------------------------------------------------
// Fused QKV projection: 1-D grid of 768 CTAs.
//   [0,512):   Q -> x2 mainloop, rope + fp16 hi/lo out
//   [512,640): K -> x1 mainloop (xhi only), rope + fp16 single out
//   [640,768): V -> x1 mainloop (xhi only), fp16 single out
// ---------------------------------------------------------------------------
__global__ __launch_bounds__(256) void gemm_qkv(
    const __half* __restrict__ xhi, const __half* __restrict__ xlo,
    const __half* __restrict__ wq, const __half* __restrict__ wk,
    const __half* __restrict__ wv,
    __half* __restrict__ qh, __half* __restrict__ ql,
    __half* __restrict__ kf, __half* __restrict__ vf,
    const float2* __restrict__ rope)
{
    extern __shared__ char dsm[];
    const uint32_t sBase = smem_u32(dsm);

    const int tid  = threadIdx.x;
    const int lane = tid & 31;
    const int wid  = tid >> 5;
    const int wr   = wid >> 2;
    const int wc   = wid & 3;

    const int bid = blockIdx.x;
    const __half* Bs;
    int row0, col0, N, mode;   // 0=Q rope hi/lo, 1=K rope single, 2=V single
    if (bid < 512) {
        row0 = (bid >> 4) * 128; col0 = (bid & 15) * 128;
        Bs = wq; N = NQ; mode = 0;
    } else if (bid < 640) {
        int i = bid - 512;
        row0 = (i >> 2) * 128; col0 = (i & 3) * 128;
        Bs = wk; N = NKV; mode = 1;
    } else {
        int i = bid - 640;
        row0 = (i >> 2) * 128; col0 = (i & 3) * 128;
        Bs = wv; N = NKV; mode = 2;
    }

    float acc[4][4][4];
#pragma unroll
    for (int i = 0; i < 4; i++)
#pragma unroll
        for (int j = 0; j < 4; j++)
#pragma unroll
            for (int l = 0; l < 4; l++) acc[i][j][l] = 0.0f;

    if (mode == 0)
        gemm_mainloop(sBase, xhi, xlo, Bs, row0, col0, tid, lane, wr, wc, acc);
    else
        gemm_mainloop_x1(sBase, xhi, Bs, row0, col0, tid, lane, wr, wc, acc);

    const int rbase = row0 + wr * 64;
    const int cbase = col0 + wc * 32;
#pragma unroll
    for (int am = 0; am < 4; am++)
#pragma unroll
        for (int an = 0; an < 4; an++) {
            float* cf = acc[am][an];
            int r  = rbase + am * 16 + (lane >> 2);
            int cc = cbase + an * 8 + (lane & 3) * 2;
            if (mode == 2) {
                *(__half2*)(vf + (size_t)r * N + cc)       = __floats2half2_rn(cf[0], cf[1]);
                *(__half2*)(vf + (size_t)(r + 8) * N + cc) = __floats2half2_rn(cf[2], cf[3]);
            } else {
                int p = (cc & 127) >> 1;
                float2 cs0 = rope[(size_t)(r & (SS - 1)) * 64 + p];
                float2 cs1 = rope[(size_t)((r + 8) & (SS - 1)) * 64 + p];
                float o0 = cf[0] * cs0.x - cf[1] * cs0.y;
                float o1 = cf[0] * cs0.y + cf[1] * cs0.x;
                float o2 = cf[2] * cs1.x - cf[3] * cs1.y;
                float o3 = cf[2] * cs1.y + cf[3] * cs1.x;
                if (mode == 0) {
                    store_hilo_h(qh, ql, (size_t)r * N + cc,       o0, o1);
                    store_hilo_h(qh, ql, (size_t)(r + 8) * N + cc, o2, o3);
                } else {
                    *(__half2*)(kf + (size_t)r * N + cc)       = __floats2half2_rn(o0, o1);
                    *(__half2*)(kf + (size_t)(r + 8) * N + cc) = __floats2half2_rn(o2, o3);
                }
            }
        }
}

// ---------------------------------------------------------------------------
// O-projection GEMM: A single fp16, fp32 C output
// ---------------------------------------------------------------------------
__global__ __launch_bounds__(256) void gemm_oproj(
    const __half* __restrict__ As, const __half* __restrict__ Bs,
    float* __restrict__ C, int N)
{
    extern __shared__ char dsm[];
    const uint32_t sBase = smem_u32(dsm);

    const int tid  = threadIdx.x;
    const int lane = tid & 31;
    const int wid  = tid >> 5;
    const int wr   = wid >> 2;
    const int wc   = wid & 3;
    const int row0 = blockIdx.y * 128;
    const int col0 = blockIdx.x * 128;

    float acc[4][4][4];
#pragma unroll
    for (int i = 0; i < 4; i++)
#pragma unroll
        for (int j = 0; j < 4; j++)
#pragma unroll
            for (int l = 0; l < 4; l++) acc[i][j][l] = 0.0f;

    gemm_mainloop_x1(sBase, As, Bs, row0, col0, tid, lane, wr, wc, acc);

    const int rbase = row0 + wr * 64;
    const int cbase = col0 + wc * 32;
#pragma unroll
    for (int am = 0; am < 4; am++)
#pragma unroll
        for (int an = 0; an < 4; an++) {
            float* cf = acc[am][an];
            int r  = rbase + am * 16 + (lane >> 2);
            int cc = cbase + an * 8 + (lane & 3) * 2;
            *(float2*)(C + (size_t)r * N + cc)       = make_float2(cf[0], cf[1]);
            *(float2*)(C + (size_t)(r + 8) * N + cc) = make_float2(cf[2], cf[3]);
        }
}

// ---------------------------------------------------------------------------
// Merged prep: rope table + x fp16 hi/lo split + 4 weight transposes (fp16)
// ---------------------------------------------------------------------------
#define PREP_GRID 27136

__device__ __forceinline__ void transpose_tile_h(
    const float* __restrict__ src, __half* __restrict__ dst,
    int N, int bx, int by, float (*t)[33], int tx, int ty)
{
    int k0 = by * 32, n0 = bx * 32;
#pragma unroll
    for (int j = 0; j < 32; j += 8)
        t[ty + j][tx] = src[(size_t)(k0 + ty + j) * N + n0 + tx];
    __syncthreads();
#pragma unroll
    for (int j = 0; j < 32; j += 8)
        dst[(size_t)(n0 + ty + j) * KK + k0 + tx] = __float2half(t[tx][ty + j]);
}

__global__ __launch_bounds__(256) void prep_kernel(
    const float* __restrict__ x,
    __half2* __restrict__ xhi2, __half2* __restrict__ xlo2,
    const float* __restrict__ Wq, const float* __restrict__ Wk,
    const float* __restrict__ Wv, const float* __restrict__ Wo,
    __half* __restrict__ wq, __half* __restrict__ wk,
    __half* __restrict__ wv, __half* __restrict__ wo,
    float2* __restrict__ ropet)
{
    __shared__ float t[32][33];
    const int bid = blockIdx.x;
    const int tid = threadIdx.x;

    if (bid < 512) {
        int i = bid * 256 + tid;
        int s = i >> 6, p = i & 63;
        float e   = (float)(2 * p) * (1.0f / 128.0f);
        float inv = 1.0f / powf(10000.0f, e);
        float sn, c;
        sincosf((float)s * inv, &sn, &c);
        ropet[i] = make_float2(c, sn);
    } else if (bid < 16896) {
        int i = (bid - 512) * 256 + tid;
        float2 v = ((const float2*)x)[i];
        __half hx = __float2half(v.x);
        __half hy = __float2half(v.y);
        xhi2[i] = __halves2half2(hx, hy);
        xlo2[i] = __halves2half2(__float2half(v.x - __half2float(hx)),
                                 __float2half(v.y - __half2float(hy)));
    } else {
        int r = bid - 16896;
        int tx = tid & 31, ty = tid >> 5;
        if (r < 4096)
            transpose_tile_h(Wq, wq, NQ,  r & 63, r >> 6, t, tx, ty);
        else if (r < 5120)
            transpose_tile_h(Wk, wk, NKV, (r - 4096) & 15, (r - 4096) >> 4, t, tx, ty);
        else if (r < 6144)
            transpose_tile_h(Wv, wv, NKV, (r - 5120) & 15, (r - 5120) >> 4, t, tx, ty);
        else
            transpose_tile_h(Wo, wo, NQ,  (r - 6144) & 63, (r - 6144) >> 6, t, tx, ty);
    }
}

// ---------------------------------------------------------------------------
// Flash attention: S = Qhi·K + Qlo·K (fp16 x2), P·V fp16. Causal, GQA 4:1.
// LPT 1-D grid. 3-stage KV ring; epilogue writes single fp16.
// ---------------------------------------------------------------------------
#define AP      272
#define QTB     (128 * AP)
#define KVTB    (64 * AP)
#define KVB     (2 * QTB)
#define KVSTG   (2 * KVTB)
#define ATTN_SMEM (2 * QTB + 3 * KVSTG)   // 174080

__device__ __forceinline__ void load_kv_tile(uint32_t sb, uint32_t stg,
    const __half* kf, const __half* vf, int k0, int tid)
{
#pragma unroll
    for (int t = 0; t < 8; t++) {
        int i  = tid + t * 256;
        int m  = i >> 10;
        int w  = i & 1023;
        int r  = w >> 4;
        int sg = w & 15;
        const __half* src = m ? vf : kf;
        cp16(sb + stg + (uint32_t)m * KVTB + (uint32_t)(r * AP + sg * 16),
             src + (size_t)(k0 + r) * NKV + sg * 8);
    }
}

__global__ __launch_bounds__(256) void attn_mma(
    const __half* __restrict__ qhi, const __half* __restrict__ qlo,
    const __half* __restrict__ kf, const __half* __restrict__ vf,
    __half* __restrict__ oa)
{
    extern __shared__ char sm[];
    const uint32_t sb = smem_u32(sm);

    const int bid = blockIdx.x;
    const int qt  = (SS / 128 - 1) - (bid >> 5);
    const int hb  = bid & 31;
    const int h   = hb & 15;
    const int b   = hb >> 4;
    const int kvh = h >> 2;
    const int q0  = qt * 128;

    const int tid  = threadIdx.x;
    const int lane = tid & 31;
    const int wid  = tid >> 5;
    const int wq0  = wid * 16;
    const int gr   = lane >> 2;

    const __half* qhb = qhi + ((size_t)b * SS + q0) * NQ + h * HDIM;
    const __half* qlb = qlo + ((size_t)b * SS + q0) * NQ + h * HDIM;
    const __half* kfb = kf + (size_t)b * SS * NKV + kvh * HDIM;
    const __half* vfb = vf + (size_t)b * SS * NKV + kvh * HDIM;

    const int ntiles = 2 * qt + 2;

#pragma unroll
    for (int t = 0; t < 16; t++) {
        int i   = tid + t * 256;
        int hl  = i >> 11;
        int w   = i & 2047;
        int r   = w >> 4;
        int sg  = w & 15;
        const __half* src = hl ? qlb : qhb;
        cp16(sb + (uint32_t)hl * QTB + (uint32_t)(r * AP + sg * 16),
             src + (size_t)r * NQ + sg * 8);
    }
    load_kv_tile(sb, KVB, kfb, vfb, 0, tid);
    CP_COMMIT();
    load_kv_tile(sb, KVB + KVSTG, kfb, vfb, 64, tid);
    CP_COMMIT();

    float oacc[16][4];
#pragma unroll
    for (int j = 0; j < 16; j++)
#pragma unroll
        for (int e = 0; e < 4; e++) oacc[j][e] = 0.0f;
    float mA = -1e30f, mB = -1e30f, lA = 0.0f, lB = 0.0f;

    const float scale = 0.08838834764831845f;
    const int rAg = q0 + wq0 + gr;
    const int rBg = rAg + 8;

#pragma unroll 1
    for (int t = 0; t < ntiles; t++) {
        if (t + 2 < ntiles) {
            load_kv_tile(sb, KVB + (uint32_t)((t + 2) % 3) * KVSTG,
                         kfb, vfb, (t + 2) * 64, tid);
            CP_COMMIT();
            CP_WAIT(2);
        } else if (t + 1 < ntiles) {
            CP_WAIT(1);
        } else {
            CP_WAIT(0);
        }
        __syncthreads();

        const uint32_t kv = sb + KVB + (uint32_t)(t % 3) * KVSTG;

        // ---- S = Q @ K^T (fp16 x2) ----
        float sacc[8][4];
#pragma unroll
        for (int j = 0; j < 8; j++)
#pragma unroll
            for (int e = 0; e < 4; e++) sacc[j][e] = 0.0f;

        const uint32_t aB = sb + (uint32_t)wq0 * AP;
#pragma unroll
        for (int c = 0; c < 8; c++) {
            const uint32_t ao = (uint32_t)((lane & 15) * AP
                              + (c * 16 + ((lane >> 4) << 3)) * 2);
            uint32_t ah0, ah1, ah2, ah3, al0, al1, al2, al3;
            ldm_x4(ah0, ah1, ah2, ah3, aB + ao);
            ldm_x4(al0, al1, al2, al3, aB + QTB + ao);
#pragma unroll
            for (int g = 0; g < 4; g++) {
                const uint32_t bo = (uint32_t)((g * 16 + ((lane >> 4) << 3) + (lane & 7)) * AP
                                  + (c * 16 + ((lane >> 3) & 1) * 8) * 2);
                uint32_t bh0, bh1, bh2, bh3;
                ldm_x4(bh0, bh1, bh2, bh3, kv + bo);
                mma16816h(sacc[2 * g],     ah0, ah1, ah2, ah3, bh0, bh1);
                mma16816h(sacc[2 * g + 1], ah0, ah1, ah2, ah3, bh2, bh3);
                mma16816h(sacc[2 * g],     al0, al1, al2, al3, bh0, bh1);
                mma16816h(sacc[2 * g + 1], al0, al1, al2, al3, bh2, bh3);
            }
        }

#pragma unroll
        for (int j = 0; j < 8; j++)
#pragma unroll
            for (int e = 0; e < 4; e++) sacc[j][e] *= scale;

        if (t >= 2 * qt) {
#pragma unroll
            for (int j = 0; j < 8; j++) {
                int col = t * 64 + j * 8 + 2 * (lane & 3);
                if (col     > rAg) sacc[j][0] = -1e30f;
                if (col + 1 > rAg) sacc[j][1] = -1e30f;
                if (col     > rBg) sacc[j][2] = -1e30f;
                if (col + 1 > rBg) sacc[j][3] = -1e30f;
            }
        }

        // ---- online softmax ----
        float mxA = -1e30f, mxB = -1e30f;
#pragma unroll
        for (int j = 0; j < 8; j++) {
            mxA = fmaxf(mxA, fmaxf(sacc[j][0], sacc[j][1]));
            mxB = fmaxf(mxB, fmaxf(sacc[j][2], sacc[j][3]));
        }
        mxA = fmaxf(mxA, __shfl_xor_sync(0xffffffffu, mxA, 1));
        mxA = fmaxf(mxA, __shfl_xor_sync(0xffffffffu, mxA, 2));
        mxB = fmaxf(mxB, __shfl_xor_sync(0xffffffffu, mxB, 1));
        mxB = fmaxf(mxB, __shfl_xor_sync(0xffffffffu, mxB, 2));

        float mnA = fmaxf(mA, mxA), mnB = fmaxf(mB, mxB);
        float facA = __expf(mA - mnA), facB = __expf(mB - mnB);
        float sA = 0.0f, sB = 0.0f;
#pragma unroll
        for (int j = 0; j < 8; j++) {
            float p0 = __expf(sacc[j][0] - mnA);
            float p1 = __expf(sacc[j][1] - mnA);
            float p2 = __expf(sacc[j][2] - mnB);
            float p3 = __expf(sacc[j][3] - mnB);
            sacc[j][0] = p0; sacc[j][1] = p1; sacc[j][2] = p2; sacc[j][3] = p3;
            sA += p0 + p1; sB += p2 + p3;
        }
        sA += __shfl_xor_sync(0xffffffffu, sA, 1);
        sA += __shfl_xor_sync(0xffffffffu, sA, 2);
        sB += __shfl_xor_sync(0xffffffffu, sB, 1);
        sB += __shfl_xor_sync(0xffffffffu, sB, 2);
        lA = lA * facA + sA; lB = lB * facB + sB;
        mA = mnA; mB = mnB;
#pragma unroll
        for (int j = 0; j < 16; j++) {
            oacc[j][0] *= facA; oacc[j][1] *= facA;
            oacc[j][2] *= facB; oacc[j][3] *= facB;
        }

        // ---- O += P @ V (single fp16 pass) ----
#pragma unroll
        for (int kc = 0; kc < 4; kc++) {
            const int j0 = 2 * kc, j1 = 2 * kc + 1;
            uint32_t ph[4];
            ph[0] = pack_h2(sacc[j0][0], sacc[j0][1]);
            ph[1] = pack_h2(sacc[j0][2], sacc[j0][3]);
            ph[2] = pack_h2(sacc[j1][0], sacc[j1][1]);
            ph[3] = pack_h2(sacc[j1][2], sacc[j1][3]);
#pragma unroll
            for (int bn = 0; bn < 8; bn++) {
                const uint32_t rowsel =
                    (uint32_t)((kc * 16 + ((lane >> 4) << 3) + (lane & 7)) * AP
                             + (bn * 16 + ((lane >> 3) & 1) * 8) * 2);
                uint32_t r0, r1, r2, r3;
                ldm_x4_t(r0, r1, r2, r3, kv + KVTB + rowsel);
                mma16816h(oacc[2 * bn],     ph[0], ph[1], ph[2], ph[3], r0, r2);
                mma16816h(oacc[2 * bn + 1], ph[0], ph[1], ph[2], ph[3], r1, r3);
            }
        }
        __syncthreads();
    }

    const float invA = 1.0f / lA, invB = 1.0f / lB;
    const size_t rowA = ((size_t)b * SS + rAg) * NQ;
    const size_t rowB = ((size_t)b * SS + rBg) * NQ;
#pragma unroll
    for (int j = 0; j < 16; j++) {
        int col = h * HDIM + j * 8 + 2 * (lane & 3);
        *(__half2*)(oa + rowA + col) = __floats2half2_rn(oacc[j][0] * invA, oacc[j][1] * invA);
        *(__half2*)(oa + rowB + col) = __floats2half2_rn(oacc[j][2] * invB, oacc[j][3] * invB);
    }
}

// ---------------------------------------------------------------------------
extern "C" void kernel_launch(void* const* d_in, const int* in_sizes, int n_in,
                              void* d_out, int out_size)
{
    const float* x  = (const float*)d_in[0];
    const float* Wq = (const float*)d_in[2];
    const float* Wk = (const float*)d_in[3];
    const float* Wv = (const float*)d_in[4];
    const float* Wo = (const float*)d_in[5];
    float* out = (float*)d_out;

    __half *xhi, *xlo, *af, *qh, *ql, *kf, *vf;
    __half *wq, *wk, *wv, *wo;
    float2* rope;
    (void)cudaGetSymbolAddress((void**)&xhi, g_xhi);
    (void)cudaGetSymbolAddress((void**)&xlo, g_xlo);
    (void)cudaGetSymbolAddress((void**)&af, g_af);
    (void)cudaGetSymbolAddress((void**)&qh, g_qhi);
    (void)cudaGetSymbolAddress((void**)&ql, g_qlo);
    (void)cudaGetSymbolAddress((void**)&kf, g_kf);
    (void)cudaGetSymbolAddress((void**)&vf, g_vf);
    (void)cudaGetSymbolAddress((void**)&wq, g_wqT);
    (void)cudaGetSymbolAddress((void**)&wk, g_wkT);
    (void)cudaGetSymbolAddress((void**)&wv, g_wvT);
    (void)cudaGetSymbolAddress((void**)&wo, g_woT);
    (void)cudaGetSymbolAddress((void**)&rope, g_rope);

    (void)cudaFuncSetAttribute(gemm_qkv,
                               cudaFuncAttributeMaxDynamicSharedMemorySize, GEMM_DSMEM);
    (void)cudaFuncSetAttribute(gemm_oproj,
                               cudaFuncAttributeMaxDynamicSharedMemorySize, GEMM1_DSMEM);
    (void)cudaFuncSetAttribute(attn_mma,
                               cudaFuncAttributeMaxDynamicSharedMemorySize, ATTN_SMEM);

    // 1) merged prep
    prep_kernel<<<PREP_GRID, 256>>>(x,
                                    (__half2*)xhi, (__half2*)xlo,
                                    Wq, Wk, Wv, Wo,
                                    wq, wk, wv, wo, rope);

    // 2) fused QKV projection (Q: fp16 x2; K,V: fp16 x1) — BK=64 staging
    gemm_qkv<<<768, 256, GEMM_DSMEM>>>(xhi, xlo, wq, wk, wv,
                                       qh, ql, kf, vf, rope);

    // 3) attention (fp16 x2 S, fp16 PV); writes single-fp16 attention output
    attn_mma<<<(SS / 128) * NHQ * BB, 256, ATTN_SMEM>>>(qh, ql, kf, vf, af);

    // 4) output projection (fp16 x1) -> fp32 out — BK=64 staging
    gemm_oproj<<<dim3(NQ / 128, MM / 128), 256, GEMM1_DSMEM>>>(af, wo, out, NQ);
}

// round 15
// speedup vs baseline: 2.3477x; 1.2503x over previous
#include <cuda_runtime.h>
#include <cuda_bf16.h>
#include <cuda_fp16.h>
#include <math.h>
#include <stdint.h>

#define BB   2
#define SS   2048
#define DD   2048
#define NHQ  16
#define NKVH 4
#define HDIM 128
#define MM   (BB*SS)       // 4096
#define KK   2048
#define NQ   (NHQ*HDIM)    // 2048
#define NKV  (NKVH*HDIM)   // 512

// ---------------- scratch (device globals; no allocation allowed) ----------
__device__ __half g_xf[(size_t)MM*KK];                 // x fp16 single
__device__ __half g_af[(size_t)MM*NQ];                 // attention out, fp16
__device__ __half g_qf[(size_t)MM*NQ];                 // Q fp16 single (roped)
__device__ __half g_kf[(size_t)MM*NKV];                // K fp16 single (roped)
__device__ __half g_vf[(size_t)MM*NKV];                // V fp16 single
__device__ __half g_wqT[(size_t)NQ*KK];
__device__ __half g_wkT[(size_t)NKV*KK];
__device__ __half g_wvT[(size_t)NKV*KK];
__device__ __half g_woT[(size_t)NQ*KK];
__device__ float2 g_rope[(size_t)SS*64];               // (cos, sin)

// ---------------- PTX helpers ----------------------------------------------
__device__ __forceinline__ uint32_t smem_u32(const void* p) {
    uint32_t a;
    asm("{ .reg .u64 t; cvta.to.shared.u64 t, %1; cvt.u32.u64 %0, t; }"
        : "=r"(a) : "l"(p));
    return a;
}

__device__ __forceinline__ void cp16(uint32_t s, const void* g) {
    asm volatile("cp.async.cg.shared.global [%0], [%1], 16;" :: "r"(s), "l"(g));
}
#define CP_COMMIT() asm volatile("cp.async.commit_group;" ::: "memory")
#define CP_WAIT(n)  asm volatile("cp.async.wait_group %0;" :: "n"(n) : "memory")

__device__ __forceinline__ void ldm_x4(uint32_t& r0, uint32_t& r1,
                                       uint32_t& r2, uint32_t& r3, uint32_t a) {
    asm volatile("ldmatrix.sync.aligned.m8n8.x4.shared.b16 {%0,%1,%2,%3}, [%4];"
                 : "=r"(r0), "=r"(r1), "=r"(r2), "=r"(r3) : "r"(a));
}
__device__ __forceinline__ void ldm_x4_t(uint32_t& r0, uint32_t& r1,
                                         uint32_t& r2, uint32_t& r3, uint32_t a) {
    asm volatile("ldmatrix.sync.aligned.m8n8.x4.trans.shared.b16 {%0,%1,%2,%3}, [%4];"
                 : "=r"(r0), "=r"(r1), "=r"(r2), "=r"(r3) : "r"(a));
}

__device__ __forceinline__ void mma16816h(float* c,
    uint32_t a0, uint32_t a1, uint32_t a2, uint32_t a3, uint32_t b0, uint32_t b1)
{
    asm volatile(
        "mma.sync.aligned.m16n8k16.row.col.f32.f16.f16.f32 "
        "{%0,%1,%2,%3}, {%4,%5,%6,%7}, {%8,%9}, {%0,%1,%2,%3};"
        : "+f"(c[0]), "+f"(c[1]), "+f"(c[2]), "+f"(c[3])
        : "r"(a0), "r"(a1), "r"(a2), "r"(a3), "r"(b0), "r"(b1));
}

__device__ __forceinline__ uint32_t pack_h2(float x, float y) {
    __half2 t = __floats2half2_rn(x, y);
    return *reinterpret_cast<uint32_t*>(&t);
}

// ---------------------------------------------------------------------------
// GEMM machinery (fp16 x1: A single + B single). BK=64, pitch 144 B,
// 2-stage cp.async. Stage = 2 tiles.
// ---------------------------------------------------------------------------
#define BK        64
#define ROWB      144                  // 64 halves (128 B) + 16 pad
#define TILEB     (128 * ROWB)         // 18432
#define OFF_B1    (TILEB)
#define STAGEB1   (2 * TILEB)          // 36864
#define GEMM1_DSMEM (2 * STAGEB1)      // 73728
#define NCHUNK    (KK / BK)            // 32

__device__ __forceinline__ void load_stage1(uint32_t sBase,
    const __half* As, const __half* Bs,
    int row0, int col0, int k0, int tid)
{
#pragma unroll
    for (int t = 0; t < 8; t++) {
        int i    = tid + t * 256;
        int tile = i >> 10;                // constant per unrolled t
        int w    = i & 1023;
        int r    = w >> 3;
        int sg   = w & 7;
        const __half* src = (tile == 0) ? As : Bs;
        int rb = (tile == 0) ? row0 : col0;
        cp16(sBase + tile * TILEB + r * ROWB + sg * 16,
             src + (size_t)(rb + r) * KK + k0 + sg * 8);
    }
}

__device__ __forceinline__ void gemm_mainloop_x1(uint32_t sBase,
    const __half* As, const __half* Bs,
    int row0, int col0, int tid, int lane, int wr, int wc,
    float acc[4][4][4])
{
    load_stage1(sBase, As, Bs, row0, col0, 0, tid);
    CP_COMMIT();

#pragma unroll 1
    for (int c = 0; c < NCHUNK; c++) {
        const uint32_t st = sBase + (uint32_t)(c & 1) * STAGEB1;
        if (c + 1 < NCHUNK) {
            load_stage1(sBase + (uint32_t)((c + 1) & 1) * STAGEB1,
                        As, Bs, row0, col0, (c + 1) * BK, tid);
            CP_COMMIT();
            CP_WAIT(1);
        } else {
            CP_WAIT(0);
        }
        __syncthreads();

        const uint32_t aW = st + (uint32_t)(wr * 64) * ROWB;
        const uint32_t bW = st + OFF_B1 + (uint32_t)(wc * 32) * ROWB;

#pragma unroll
        for (int ks = 0; ks < 4; ks++) {
            const uint32_t aoff = (uint32_t)((lane & 15) * ROWB
                                + (ks * 16 + ((lane >> 4) << 3)) * 2);
            uint32_t A[4][4];
#pragma unroll
            for (int am = 0; am < 4; am++)
                ldm_x4(A[am][0], A[am][1], A[am][2], A[am][3],
                       aW + (uint32_t)(am * 16) * ROWB + aoff);
            const uint32_t boff = (uint32_t)((((lane >> 4) << 3) + (lane & 7)) * ROWB
                                + (ks * 16 + ((lane >> 3) & 1) * 8) * 2);
            uint32_t Bx[2][4];
#pragma unroll
            for (int bn = 0; bn < 2; bn++)
                ldm_x4(Bx[bn][0], Bx[bn][1], Bx[bn][2], Bx[bn][3],
                       bW + (uint32_t)(bn * 16) * ROWB + boff);
#pragma unroll
            for (int am = 0; am < 4; am++)
#pragma unroll
                for (int an = 0; an < 4; an++)
                    mma16816h(acc[am][an], A[am][0], A[am][1], A[am][2], A[am][3],
                              Bx[an >> 1][(an & 1) * 2], Bx[an >> 1][(an & 1) * 2 + 1]);
        }
        __syncthreads();
    }
}

// ---------------------------------------------------------------------------
// Fused QKV projection: 1-D grid of 768 CTAs, all fp16 x1.
//   [0,512):   Q -> rope + fp16 single
//   [512,640): K -> rope + fp16 single
//   [640,768): V -> fp16 single
// ---------------------------------------------------------------------------
__global__ __launch_bounds__(256) void gemm_qkv(
    const __half* __restrict__ xf,
    const __half* __restrict__ wq, const __half* __restrict__ wk,
    const __half* __restrict__ wv,
    __half* __restrict__ qf, __half* __restrict__ kf, __half* __restrict__ vf,
    const float2* __restrict__ rope)
{
    extern __shared__ char dsm[];
    const uint32_t sBase = smem_u32(dsm);

    const int tid  = threadIdx.x;
    const int lane = tid & 31;
    const int wid  = tid >> 5;
    const int wr   = wid >> 2;
    const int wc   = wid & 3;

    const int bid = blockIdx.x;
    const __half* Bs;
    __half* Of;
    int row0, col0, N, do_rope;
    if (bid < 512) {
        row0 = (bid >> 4) * 128; col0 = (bid & 15) * 128;
        Bs = wq; Of = qf; N = NQ; do_rope = 1;
    } else if (bid < 640) {
        int i = bid - 512;
        row0 = (i >> 2) * 128; col0 = (i & 3) * 128;
        Bs = wk; Of = kf; N = NKV; do_rope = 1;
    } else {
        int i = bid - 640;
        row0 = (i >> 2) * 128; col0 = (i & 3) * 128;
        Bs = wv; Of = vf; N = NKV; do_rope = 0;
    }

    float acc[4][4][4];
#pragma unroll
    for (int i = 0; i < 4; i++)
#pragma unroll
        for (int j = 0; j < 4; j++)
#pragma unroll
            for (int l = 0; l < 4; l++) acc[i][j][l] = 0.0f;

    gemm_mainloop_x1(sBase, xf, Bs, row0, col0, tid, lane, wr, wc, acc);

    const int rbase = row0 + wr * 64;
    const int cbase = col0 + wc * 32;
#pragma unroll
    for (int am = 0; am < 4; am++)
#pragma unroll
        for (int an = 0; an < 4; an++) {
            float* cf = acc[am][an];
            int r  = rbase + am * 16 + (lane >> 2);
            int cc = cbase + an * 8 + (lane & 3) * 2;
            if (do_rope) {
                int p = (cc & 127) >> 1;
                float2 cs0 = rope[(size_t)(r & (SS - 1)) * 64 + p];
                float2 cs1 = rope[(size_t)((r + 8) & (SS - 1)) * 64 + p];
                float o0 = cf[0] * cs0.x - cf[1] * cs0.y;
                float o1 = cf[0] * cs0.y + cf[1] * cs0.x;
                float o2 = cf[2] * cs1.x - cf[3] * cs1.y;
                float o3 = cf[2] * cs1.y + cf[3] * cs1.x;
                *(__half2*)(Of + (size_t)r * N + cc)       = __floats2half2_rn(o0, o1);
                *(__half2*)(Of + (size_t)(r + 8) * N + cc) = __floats2half2_rn(o2, o3);
            } else {
                *(__half2*)(Of + (size_t)r * N + cc)       = __floats2half2_rn(cf[0], cf[1]);
                *(__half2*)(Of + (size_t)(r + 8) * N + cc) = __floats2half2_rn(cf[2], cf[3]);
            }
        }
}

// ---------------------------------------------------------------------------
// O-projection GEMM: A single fp16, fp32 C output
// ---------------------------------------------------------------------------
__global__ __launch_bounds__(256) void gemm_oproj(
    const __half* __restrict__ As, const __half* __restrict__ Bs,
    float* __restrict__ C, int N)
{
    extern __shared__ char dsm[];
    const uint32_t sBase = smem_u32(dsm);

    const int tid  = threadIdx.x;
    const int lane = tid & 31;
    const int wid  = tid >> 5;
    const int wr   = wid >> 2;
    const int wc   = wid & 3;
    const int row0 = blockIdx.y * 128;
    const int col0 = blockIdx.x * 128;

    float acc[4][4][4];
#pragma unroll
    for (int i = 0; i < 4; i++)
#pragma unroll
        for (int j = 0; j < 4; j++)
#pragma unroll
            for (int l = 0; l < 4; l++) acc[i][j][l] = 0.0f;

    gemm_mainloop_x1(sBase, As, Bs, row0, col0, tid, lane, wr, wc, acc);

    const int rbase = row0 + wr * 64;
    const int cbase = col0 + wc * 32;
#pragma unroll
    for (int am = 0; am < 4; am++)
#pragma unroll
        for (int an = 0; an < 4; an++) {
            float* cf = acc[am][an];
            int r  = rbase + am * 16 + (lane >> 2);
            int cc = cbase + an * 8 + (lane & 3) * 2;
            *(float2*)(C + (size_t)r * N + cc)       = make_float2(cf[0], cf[1]);
            *(float2*)(C + (size_t)(r + 8) * N + cc) = make_float2(cf[2], cf[3]);
        }
}

// ---------------------------------------------------------------------------
// Merged prep: rope table + x fp16 cast + 4 weight transposes (fp16)
//   [0,512):       rope table
//   [512,16896):   x fp32 -> fp16
//   [16896,20992): Wq   [20992,22016): Wk   [22016,23040): Wv   [23040,27136): Wo
// ---------------------------------------------------------------------------
#define PREP_GRID 27136

__device__ __forceinline__ void transpose_tile_h(
    const float* __restrict__ src, __half* __restrict__ dst,
    int N, int bx, int by, float (*t)[33], int tx, int ty)
{
    int k0 = by * 32, n0 = bx * 32;
#pragma unroll
    for (int j = 0; j < 32; j += 8)
        t[ty + j][tx] = src[(size_t)(k0 + ty + j) * N + n0 + tx];
    __syncthreads();
#pragma unroll
    for (int j = 0; j < 32; j += 8)
        dst[(size_t)(n0 + ty + j) * KK + k0 + tx] = __float2half(t[tx][ty + j]);
}

__global__ __launch_bounds__(256) void prep_kernel(
    const float* __restrict__ x, __half2* __restrict__ xf2,
    const float* __restrict__ Wq, const float* __restrict__ Wk,
    const float* __restrict__ Wv, const float* __restrict__ Wo,
    __half* __restrict__ wq, __half* __restrict__ wk,
    __half* __restrict__ wv, __half* __restrict__ wo,
    float2* __restrict__ ropet)
{
    __shared__ float t[32][33];
    const int bid = blockIdx.x;
    const int tid = threadIdx.x;

    if (bid < 512) {
        int i = bid * 256 + tid;
        int s = i >> 6, p = i & 63;
        float e   = (float)(2 * p) * (1.0f / 128.0f);
        float inv = 1.0f / powf(10000.0f, e);
        float sn, c;
        sincosf((float)s * inv, &sn, &c);
        ropet[i] = make_float2(c, sn);
    } else if (bid < 16896) {
        int i = (bid - 512) * 256 + tid;
        float2 v = ((const float2*)x)[i];
        xf2[i] = __floats2half2_rn(v.x, v.y);
    } else {
        int r = bid - 16896;
        int tx = tid & 31, ty = tid >> 5;
        if (r < 4096)
            transpose_tile_h(Wq, wq, NQ,  r & 63, r >> 6, t, tx, ty);
        else if (r < 5120)
            transpose_tile_h(Wk, wk, NKV, (r - 4096) & 15, (r - 4096) >> 4, t, tx, ty);
        else if (r < 6144)
            transpose_tile_h(Wv, wv, NKV, (r - 5120) & 15, (r - 5120) >> 4, t, tx, ty);
        else
            transpose_tile_h(Wo, wo, NQ,  (r - 6144) & 63, (r - 6144) >> 6, t, tx, ty);
    }
}

// ---------------------------------------------------------------------------
// Flash attention: S = Q·K^T fp16 x1, P·V fp16. Causal, GQA 4:1.
// LPT 1-D grid. Q single tile resident; 3-stage KV ring.
// ---------------------------------------------------------------------------
#define AP      272
#define QTB     (128 * AP)                // 34816 (single Q tile)
#define KVTB    (64 * AP)                 // 17408
#define KVB     (QTB)
#define KVSTG   (2 * KVTB)                // 34816
#define ATTN_SMEM (QTB + 3 * KVSTG)       // 139264

__device__ __forceinline__ void load_kv_tile(uint32_t sb, uint32_t stg,
    const __half* kf, const __half* vf, int k0, int tid)
{
#pragma unroll
    for (int t = 0; t < 8; t++) {
        int i  = tid + t * 256;
        int m  = i >> 10;
        int w  = i & 1023;
        int r  = w >> 4;
        int sg = w & 15;
        const __half* src = m ? vf : kf;
        cp16(sb + stg + (uint32_t)m * KVTB + (uint32_t)(r * AP + sg * 16),
             src + (size_t)(k0 + r) * NKV + sg * 8);
    }
}

__global__ __launch_bounds__(256) void attn_mma(
    const __half* __restrict__ qf,
    const __half* __restrict__ kf, const __half* __restrict__ vf,
    __half* __restrict__ oa)
{
    extern __shared__ char sm[];
    const uint32_t sb = smem_u32(sm);

    const int bid = blockIdx.x;
    const int qt  = (SS / 128 - 1) - (bid >> 5);
    const int hb  = bid & 31;
    const int h   = hb & 15;
    const int b   = hb >> 4;
    const int kvh = h >> 2;
    const int q0  = qt * 128;

    const int tid  = threadIdx.x;
    const int lane = tid & 31;
    const int wid  = tid >> 5;
    const int wq0  = wid * 16;
    const int gr   = lane >> 2;

    const __half* qfb = qf + ((size_t)b * SS + q0) * NQ + h * HDIM;
    const __half* kfb = kf + (size_t)b * SS * NKV + kvh * HDIM;
    const __half* vfb = vf + (size_t)b * SS * NKV + kvh * HDIM;

    const int ntiles = 2 * qt + 2;

    // Q tile (single) + KV tiles 0,1
#pragma unroll
    for (int t = 0; t < 8; t++) {
        int i  = tid + t * 256;
        int r  = i >> 4;
        int sg = i & 15;
        cp16(sb + (uint32_t)(r * AP + sg * 16),
             qfb + (size_t)r * NQ + sg * 8);
    }
    load_kv_tile(sb, KVB, kfb, vfb, 0, tid);
    CP_COMMIT();
    load_kv_tile(sb, KVB + KVSTG, kfb, vfb, 64, tid);
    CP_COMMIT();

    float oacc[16][4];
#pragma unroll
    for (int j = 0; j < 16; j++)
#pragma unroll
        for (int e = 0; e < 4; e++) oacc[j][e] = 0.0f;
    float mA = -1e30f, mB = -1e30f, lA = 0.0f, lB = 0.0f;

    const float scale = 0.08838834764831845f;
    const int rAg = q0 + wq0 + gr;
    const int rBg = rAg + 8;

#pragma unroll 1
    for (int t = 0; t < ntiles; t++) {
        if (t + 2 < ntiles) {
            load_kv_tile(sb, KVB + (uint32_t)((t + 2) % 3) * KVSTG,
                         kfb, vfb, (t + 2) * 64, tid);
            CP_COMMIT();
            CP_WAIT(2);
        } else if (t + 1 < ntiles) {
            CP_WAIT(1);
        } else {
            CP_WAIT(0);
        }
        __syncthreads();

        const uint32_t kv = sb + KVB + (uint32_t)(t % 3) * KVSTG;

        // ---- S = Q @ K^T (fp16 x1) ----
        float sacc[8][4];
#pragma unroll
        for (int j = 0; j < 8; j++)
#pragma unroll
            for (int e = 0; e < 4; e++) sacc[j][e] = 0.0f;

        const uint32_t aB = sb + (uint32_t)wq0 * AP;
#pragma unroll
        for (int c = 0; c < 8; c++) {
            const uint32_t ao = (uint32_t)((lane & 15) * AP
                              + (c * 16 + ((lane >> 4) << 3)) * 2);
            uint32_t a0, a1, a2, a3;
            ldm_x4(a0, a1, a2, a3, aB + ao);
#pragma unroll
            for (int g = 0; g < 4; g++) {
                const uint32_t bo = (uint32_t)((g * 16 + ((lane >> 4) << 3) + (lane & 7)) * AP
                                  + (c * 16 + ((lane >> 3) & 1) * 8) * 2);
                uint32_t b0, b1, b2, b3;
                ldm_x4(b0, b1, b2, b3, kv + bo);
                mma16816h(sacc[2 * g],     a0, a1, a2, a3, b0, b1);
                mma16816h(sacc[2 * g + 1], a0, a1, a2, a3, b2, b3);
            }
        }

#pragma unroll
        for (int j = 0; j < 8; j++)
#pragma unroll
            for (int e = 0; e < 4; e++) sacc[j][e] *= scale;

        if (t >= 2 * qt) {
#pragma unroll
            for (int j = 0; j < 8; j++) {
                int col = t * 64 + j * 8 + 2 * (lane & 3);
                if (col     > rAg) sacc[j][0] = -1e30f;
                if (col + 1 > rAg) sacc[j][1] = -1e30f;
                if (col     > rBg) sacc[j][2] = -1e30f;
                if (col + 1 > rBg) sacc[j][3] = -1e30f;
            }
        }

        // ---- online softmax ----
        float mxA = -1e30f, mxB = -1e30f;
#pragma unroll
        for (int j = 0; j < 8; j++) {
            mxA = fmaxf(mxA, fmaxf(sacc[j][0], sacc[j][1]));
            mxB = fmaxf(mxB, fmaxf(sacc[j][2], sacc[j][3]));
        }
        mxA = fmaxf(mxA, __shfl_xor_sync(0xffffffffu, mxA, 1));
        mxA = fmaxf(mxA, __shfl_xor_sync(0xffffffffu, mxA, 2));
        mxB = fmaxf(mxB, __shfl_xor_sync(0xffffffffu, mxB, 1));
        mxB = fmaxf(mxB, __shfl_xor_sync(0xffffffffu, mxB, 2));

        float mnA = fmaxf(mA, mxA), mnB = fmaxf(mB, mxB);
        float facA = __expf(mA - mnA), facB = __expf(mB - mnB);
        float sA = 0.0f, sB = 0.0f;
#pragma unroll
        for (int j = 0; j < 8; j++) {
            float p0 = __expf(sacc[j][0] - mnA);
            float p1 = __expf(sacc[j][1] - mnA);
            float p2 = __expf(sacc[j][2] - mnB);
            float p3 = __expf(sacc[j][3] - mnB);
            sacc[j][0] = p0; sacc[j][1] = p1; sacc[j][2] = p2; sacc[j][3] = p3;
            sA += p0 + p1; sB += p2 + p3;
        }
        sA += __shfl_xor_sync(0xffffffffu, sA, 1);
        sA += __shfl_xor_sync(0xffffffffu, sA, 2);
        sB += __shfl_xor_sync(0xffffffffu, sB, 1);
        sB += __shfl_xor_sync(0xffffffffu, sB, 2);
        lA = lA * facA + sA; lB = lB * facB + sB;
        mA = mnA; mB = mnB;
#pragma unroll
        for (int j = 0; j < 16; j++) {
            oacc[j][0] *= facA; oacc[j][1] *= facA;
            oacc[j][2] *= facB; oacc[j][3] *= facB;
        }

        // ---- O += P @ V (single fp16 pass) ----
#pragma unroll
        for (int kc = 0; kc < 4; kc++) {
            const int j0 = 2 * kc, j1 = 2 * kc + 1;
            uint32_t ph[4];
            ph[0] = pack_h2(sacc[j0][0], sacc[j0][1]);
            ph[1] = pack_h2(sacc[j0][2], sacc[j0][3]);
            ph[2] = pack_h2(sacc[j1][0], sacc[j1][1]);
            ph[3] = pack_h2(sacc[j1][2], sacc[j1][3]);
#pragma unroll
            for (int bn = 0; bn < 8; bn++) {
                const uint32_t rowsel =
                    (uint32_t)((kc * 16 + ((lane >> 4) << 3) + (lane & 7)) * AP
                             + (bn * 16 + ((lane >> 3) & 1) * 8) * 2);
                uint32_t r0, r1, r2, r3;
                ldm_x4_t(r0, r1, r2, r3, kv + KVTB + rowsel);
                mma16816h(oacc[2 * bn],     ph[0], ph[1], ph[2], ph[3], r0, r2);
                mma16816h(oacc[2 * bn + 1], ph[0], ph[1], ph[2], ph[3], r1, r3);
            }
        }
        __syncthreads();
    }

    const float invA = 1.0f / lA, invB = 1.0f / lB;
    const size_t rowA = ((size_t)b * SS + rAg) * NQ;
    const size_t rowB = ((size_t)b * SS + rBg) * NQ;
#pragma unroll
    for (int j = 0; j < 16; j++) {
        int col = h * HDIM + j * 8 + 2 * (lane & 3);
        *(__half2*)(oa + rowA + col) = __floats2half2_rn(oacc[j][0] * invA, oacc[j][1] * invA);
        *(__half2*)(oa + rowB + col) = __floats2half2_rn(oacc[j][2] * invB, oacc[j][3] * invB);
    }
}

// ---------------------------------------------------------------------------
extern "C" void kernel_launch(void* const* d_in, const int* in_sizes, int n_in,
                              void* d_out, int out_size)
{
    const float* x  = (const float*)d_in[0];
    const float* Wq = (const float*)d_in[2];
    const float* Wk = (const float*)d_in[3];
    const float* Wv = (const float*)d_in[4];
    const float* Wo = (const float*)d_in[5];
    float* out = (float*)d_out;

    __half *xf, *af, *qf, *kf, *vf;
    __half *wq, *wk, *wv, *wo;
    float2* rope;
    (void)cudaGetSymbolAddress((void**)&xf, g_xf);
    (void)cudaGetSymbolAddress((void**)&af, g_af);
    (void)cudaGetSymbolAddress((void**)&qf, g_qf);
    (void)cudaGetSymbolAddress((void**)&kf, g_kf);
    (void)cudaGetSymbolAddress((void**)&vf, g_vf);
    (void)cudaGetSymbolAddress((void**)&wq, g_wqT);
    (void)cudaGetSymbolAddress((void**)&wk, g_wkT);
    (void)cudaGetSymbolAddress((void**)&wv, g_wvT);
    (void)cudaGetSymbolAddress((void**)&wo, g_woT);
    (void)cudaGetSymbolAddress((void**)&rope, g_rope);

    (void)cudaFuncSetAttribute(gemm_qkv,
                               cudaFuncAttributeMaxDynamicSharedMemorySize, GEMM1_DSMEM);
    (void)cudaFuncSetAttribute(gemm_oproj,
                               cudaFuncAttributeMaxDynamicSharedMemorySize, GEMM1_DSMEM);
    (void)cudaFuncSetAttribute(attn_mma,
                               cudaFuncAttributeMaxDynamicSharedMemorySize, ATTN_SMEM);

    // 1) merged prep (x: single fp16 cast now)
    prep_kernel<<<PREP_GRID, 256>>>(x, (__half2*)xf,
                                    Wq, Wk, Wv, Wo,
                                    wq, wk, wv, wo, rope);

    // 2) fused QKV projection (all fp16 x1, BK=64)
    gemm_qkv<<<768, 256, GEMM1_DSMEM>>>(xf, wq, wk, wv, qf, kf, vf, rope);

    // 3) attention (fp16 x1 S, fp16 PV)
    attn_mma<<<(SS / 128) * NHQ * BB, 256, ATTN_SMEM>>>(qf, kf, vf, af);

    // 4) output projection (fp16 x1) -> fp32 out
    gemm_oproj<<<dim3(NQ / 128, MM / 128), 256, GEMM1_DSMEM>>>(af, wo, out, NQ);
}